// round 3
// baseline (speedup 1.0000x reference)
#include <cuda_runtime.h>
#include <math_constants.h>

#define N     2048
#define NT    256
#define NCLS  10
#define C707  0.70710678118654752440f

// pad mapping: one extra float2 per 8 to break power-of-2-stride bank conflicts
#define F(i) ((i) + ((i) >> 3))
#define SPAD 2304

__device__ float2 g_cw1[N];   // exp(i*w1[n]), row-invariant

__global__ void vpc_init(const float* __restrict__ w) {
    int i = blockIdx.x * blockDim.x + threadIdx.x;
    if (i < N) {
        float s, c;
        sincosf(w[N + i], &s, &c);
        g_cw1[i] = make_float2(c, s);
    }
}

__device__ __forceinline__ float2 cmul(float2 a, float2 b) {
    return make_float2(a.x * b.x - a.y * b.y, a.x * b.y + a.y * b.x);
}
__device__ __forceinline__ float2 cadd(float2 a, float2 b) { return make_float2(a.x + b.x, a.y + b.y); }
__device__ __forceinline__ float2 csub(float2 a, float2 b) { return make_float2(a.x - b.x, a.y - b.y); }
__device__ __forceinline__ float2 mul_mi(float2 z) { return make_float2(z.y, -z.x); }   // z * (-i)
__device__ __forceinline__ float2 mul_pi(float2 z) { return make_float2(-z.y, z.x); }   // z * (+i)

// DFT8 (forward, W8 = e^{-i pi/4})
#define DFT8(x0,x1,x2,x3,x4,x5,x6,x7, X0,X1,X2,X3,X4,X5,X6,X7) do {            \
    float2 t0 = cadd(x0, x4), t1 = csub(x0, x4);                               \
    float2 t2 = cadd(x2, x6), t3 = csub(x2, x6);                               \
    float2 E0 = cadd(t0, t2), E2 = csub(t0, t2);                               \
    float2 E1 = cadd(t1, mul_mi(t3)), E3 = cadd(t1, mul_pi(t3));               \
    float2 s0 = cadd(x1, x5), s1 = csub(x1, x5);                               \
    float2 s2 = cadd(x3, x7), s3 = csub(x3, x7);                               \
    float2 O0 = cadd(s0, s2), O2 = csub(s0, s2);                               \
    float2 O1 = cadd(s1, mul_mi(s3)), O3 = cadd(s1, mul_pi(s3));               \
    float2 W1O = make_float2(C707 * (O1.x + O1.y), C707 * (O1.y - O1.x));      \
    float2 W2O = mul_mi(O2);                                                   \
    float2 W3O = make_float2(C707 * (O3.y - O3.x), -C707 * (O3.x + O3.y));     \
    X0 = cadd(E0, O0);  X4 = csub(E0, O0);                                     \
    X1 = cadd(E1, W1O); X5 = csub(E1, W1O);                                    \
    X2 = cadd(E2, W2O); X6 = csub(E2, W2O);                                    \
    X3 = cadd(E3, W3O); X7 = csub(E3, W3O);                                    \
} while (0)

// Register radix-8 + twiddle + scatter into dst. p = t >> SL masked.
#define STAGE8_STORE(dst, SL, t, r0,r1,r2,r3,r4,r5,r6,r7) do {                 \
    const int s_ = 1 << (SL);                                                  \
    float2 X0,X1,X2,X3,X4,X5,X6,X7;                                            \
    DFT8(r0,r1,r2,r3,r4,r5,r6,r7, X0,X1,X2,X3,X4,X5,X6,X7);                    \
    float th_ = (-(float)CUDART_PI / 1024.0f) * (float)((t) & ~(s_ - 1));      \
    float2 w1,w2,w3,w4;                                                        \
    __sincosf(th_,        &w1.y, &w1.x);                                       \
    __sincosf(2.0f * th_, &w2.y, &w2.x);                                       \
    __sincosf(3.0f * th_, &w3.y, &w3.x);                                       \
    __sincosf(4.0f * th_, &w4.y, &w4.x);                                       \
    float2 w5 = cmul(w1, w4), w6 = cmul(w2, w4), w7 = cmul(w3, w4);            \
    int ob_ = ((t) & (s_ - 1)) + (((t) >> (SL)) << ((SL) + 3));                \
    dst[F(ob_ + 0 * s_)] = X0;                                                 \
    dst[F(ob_ + 1 * s_)] = cmul(X1, w1);                                       \
    dst[F(ob_ + 2 * s_)] = cmul(X2, w2);                                       \
    dst[F(ob_ + 3 * s_)] = cmul(X3, w3);                                       \
    dst[F(ob_ + 4 * s_)] = cmul(X4, w4);                                       \
    dst[F(ob_ + 5 * s_)] = cmul(X5, w5);                                       \
    dst[F(ob_ + 6 * s_)] = cmul(X6, w6);                                       \
    dst[F(ob_ + 7 * s_)] = cmul(X7, w7);                                       \
} while (0)

#define LOAD256(src, t, r0,r1,r2,r3,r4,r5,r6,r7) do {                          \
    r0 = src[F((t) + 0 * 256)]; r1 = src[F((t) + 1 * 256)];                    \
    r2 = src[F((t) + 2 * 256)]; r3 = src[F((t) + 3 * 256)];                    \
    r4 = src[F((t) + 4 * 256)]; r5 = src[F((t) + 5 * 256)];                    \
    r6 = src[F((t) + 6 * 256)]; r7 = src[F((t) + 7 * 256)];                    \
} while (0)

__global__ __launch_bounds__(NT) void vpc_main(const float* __restrict__ x,
                                               const float* __restrict__ w,
                                               float* __restrict__ out) {
    __shared__ float2 sA[SPAD];
    __shared__ float2 sB[SPAD];

    const int tid = threadIdx.x;
    const int row = blockIdx.x;
    const bool odd = (tid & 1);
    const float* xr = x + (size_t)row * N;

    float2 r0, r1, r2, r3, r4, r5, r6, r7;

    // ---- Head: z = exp(i*(x+w0)); adjacent-pair butterfly via lane shuffle.
    // Thread owns n = tid + 256j; partner n^1 lives on lane tid^1.
#define HEAD(j, reg) do {                                                      \
        int n_ = tid + 256 * (j);                                              \
        float th_ = xr[n_] + __ldg(&w[n_]);                                    \
        float2 v_; __sincosf(th_, &v_.y, &v_.x);                               \
        float2 o_;                                                             \
        o_.x = __shfl_xor_sync(0xFFFFFFFFu, v_.x, 1);                          \
        o_.y = __shfl_xor_sync(0xFFFFFFFFu, v_.y, 1);                          \
        reg = odd ? csub(o_, v_) : cadd(v_, o_);                               \
    } while (0)
    HEAD(0, r0); HEAD(1, r1); HEAD(2, r2); HEAD(3, r3);
    HEAD(4, r4); HEAD(5, r5); HEAD(6, r6); HEAD(7, r7);
#undef HEAD

    // ---- FFT 2048 = 8*8*8*4, Stockham; registers + 3 shared exchanges ----
    STAGE8_STORE(sA, 0, tid, r0, r1, r2, r3, r4, r5, r6, r7);
    __syncthreads();
    LOAD256(sA, tid, r0, r1, r2, r3, r4, r5, r6, r7);
    STAGE8_STORE(sB, 3, tid, r0, r1, r2, r3, r4, r5, r6, r7);
    __syncthreads();
    LOAD256(sB, tid, r0, r1, r2, r3, r4, r5, r6, r7);
    STAGE8_STORE(sA, 6, tid, r0, r1, r2, r3, r4, r5, r6, r7);
    __syncthreads();

    // ---- Radix-4 final stage in registers (no twiddle), read r4 pattern ----
    {
        float2 b0 = sA[F(tid + 0 * 512)], b1 = sA[F(tid + 1 * 512)];
        float2 b2 = sA[F(tid + 2 * 512)], b3 = sA[F(tid + 3 * 512)];
        float2 c0 = sA[F(tid + 256 + 0 * 512)], c1 = sA[F(tid + 256 + 1 * 512)];
        float2 c2 = sA[F(tid + 256 + 2 * 512)], c3 = sA[F(tid + 256 + 3 * 512)];
        float2 apc = cadd(b0, b2), amc = csub(b0, b2);
        float2 bpd = cadd(b1, b3), bmd = csub(b1, b3);
        r0 = cadd(apc, bpd);               // m = tid + 0
        r2 = cadd(amc, mul_mi(bmd));       // m = tid + 512
        r4 = csub(apc, bpd);               // m = tid + 1024
        r6 = cadd(amc, mul_pi(bmd));       // m = tid + 1536
        float2 epc = cadd(c0, c2), emc = csub(c0, c2);
        float2 fpd = cadd(c1, c3), fmd = csub(c1, c3);
        r1 = cadd(epc, fpd);               // m = tid + 256
        r3 = cadd(emc, mul_mi(fmd));       // m = tid + 768
        r5 = csub(epc, fpd);               // m = tid + 1280
        r7 = cadd(emc, mul_pi(fmd));       // m = tid + 1792
    }

    // ---- Layer 1: z *= exp(i*w1); pair butterfly via lane shuffle ----
#define L1(j, reg) do {                                                        \
        float2 v_ = cmul(reg, __ldg(&g_cw1[tid + 256 * (j)]));                 \
        float2 o_;                                                             \
        o_.x = __shfl_xor_sync(0xFFFFFFFFu, v_.x, 1);                          \
        o_.y = __shfl_xor_sync(0xFFFFFFFFu, v_.y, 1);                          \
        reg = odd ? csub(o_, v_) : cadd(v_, o_);                               \
    } while (0)
    L1(0, r0); L1(1, r1); L1(2, r2); L1(3, r3);
    L1(4, r4); L1(5, r5); L1(6, r6); L1(7, r7);
#undef L1

    // ---- Final: bins 0..9. y[n] with n = 256a + tid already in registers.
    // S_j = DFT8 over a; X_k = W2048^{tid*k} * S_{k mod 8}, summed over tid.
    float2 S0, S1, S2, S3, S4, S5, S6, S7;
    DFT8(r0, r1, r2, r3, r4, r5, r6, r7, S0, S1, S2, S3, S4, S5, S6, S7);

    float2 acc[NCLS];
    {
        float2 w1t;
        __sincosf((-(float)CUDART_PI / 1024.0f) * (float)tid, &w1t.y, &w1t.x);
        float2 wk = make_float2(1.0f, 0.0f);
        acc[0] = S0;
        wk = cmul(wk, w1t); acc[1] = cmul(wk, S1);
        wk = cmul(wk, w1t); acc[2] = cmul(wk, S2);
        wk = cmul(wk, w1t); acc[3] = cmul(wk, S3);
        wk = cmul(wk, w1t); acc[4] = cmul(wk, S4);
        wk = cmul(wk, w1t); acc[5] = cmul(wk, S5);
        wk = cmul(wk, w1t); acc[6] = cmul(wk, S6);
        wk = cmul(wk, w1t); acc[7] = cmul(wk, S7);
        wk = cmul(wk, w1t); acc[8] = cmul(wk, S0);
        wk = cmul(wk, w1t); acc[9] = cmul(wk, S1);
    }

#pragma unroll
    for (int k = 0; k < NCLS; k++) {
#pragma unroll
        for (int off = 16; off > 0; off >>= 1) {
            acc[k].x += __shfl_down_sync(0xFFFFFFFFu, acc[k].x, off);
            acc[k].y += __shfl_down_sync(0xFFFFFFFFu, acc[k].y, off);
        }
    }

    __syncthreads();   // sA reads above must finish before reuse
    float2* red   = sB;
    float* logits = (float*)(sB + 8 * NCLS);
    int lane = tid & 31, wrp = tid >> 5;
    if (lane == 0) {
#pragma unroll
        for (int k = 0; k < NCLS; k++) red[wrp * NCLS + k] = acc[k];
    }
    __syncthreads();

    if (tid < NCLS) {
        float re = 0.f, im = 0.f;
#pragma unroll
        for (int wq = 0; wq < NT / 32; wq++) {
            re += red[wq * NCLS + tid].x;
            im += red[wq * NCLS + tid].y;
        }
        float r2v = re * re + im * im;
        // sin(atan2(im,re)) = im/|z|; dropped norms are positive -> phases unchanged
        logits[tid] = (r2v > 0.f) ? 5.0f * im * rsqrtf(r2v) : 0.0f;
    }
    __syncthreads();

    if (tid < NCLS) {
        float m = -1e30f;
#pragma unroll
        for (int k = 0; k < NCLS; k++) m = fmaxf(m, logits[k]);
        float sum = 0.f;
#pragma unroll
        for (int k = 0; k < NCLS; k++) sum += expf(logits[k] - m);
        out[(size_t)row * NCLS + tid] = expf(logits[tid] - m) / sum;
    }
}

extern "C" void kernel_launch(void* const* d_in, const int* in_sizes, int n_in,
                              void* d_out, int out_size) {
    const float* x = (const float*)d_in[0];     // (8192, 2048) fp32
    const float* w = (const float*)d_in[1];     // (4096,) fp32
    float* out = (float*)d_out;                 // (8192, 10) fp32

    vpc_init<<<(N + 255) / 256, 256>>>(w);
    vpc_main<<<8192, NT>>>(x, w, out);
}

// round 4
// speedup vs baseline: 1.4858x; 1.4858x over previous
#include <cuda_runtime.h>
#include <math_constants.h>

#define N     2048
#define NT    256
#define NCLS  10
#define C707  0.70710678118654752440f

// pad mapping: one extra float2 per 8 to break power-of-2-stride bank conflicts
#define F(i) ((i) + ((i) >> 3))
#define SPAD 2304

__device__ float2 g_cw1[N];   // exp(i*w1[n]), row-invariant

__global__ void vpc_init(const float* __restrict__ w) {
    int i = blockIdx.x * blockDim.x + threadIdx.x;
    if (i < N) {
        float s, c;
        sincosf(w[N + i], &s, &c);
        g_cw1[i] = make_float2(c, s);
    }
}

__device__ __forceinline__ float2 cmul(float2 a, float2 b) {
    return make_float2(a.x * b.x - a.y * b.y, a.x * b.y + a.y * b.x);
}
__device__ __forceinline__ float2 cadd(float2 a, float2 b) { return make_float2(a.x + b.x, a.y + b.y); }
__device__ __forceinline__ float2 csub(float2 a, float2 b) { return make_float2(a.x - b.x, a.y - b.y); }
__device__ __forceinline__ float2 mul_mi(float2 z) { return make_float2(z.y, -z.x); }   // z * (-i)
__device__ __forceinline__ float2 mul_pi(float2 z) { return make_float2(-z.y, z.x); }   // z * (+i)

// DFT8 (forward, W8 = e^{-i pi/4})
#define DFT8(x0,x1,x2,x3,x4,x5,x6,x7, X0,X1,X2,X3,X4,X5,X6,X7) do {            \
    float2 t0 = cadd(x0, x4), t1 = csub(x0, x4);                               \
    float2 t2 = cadd(x2, x6), t3 = csub(x2, x6);                               \
    float2 E0 = cadd(t0, t2), E2 = csub(t0, t2);                               \
    float2 E1 = cadd(t1, mul_mi(t3)), E3 = cadd(t1, mul_pi(t3));               \
    float2 s0 = cadd(x1, x5), s1 = csub(x1, x5);                               \
    float2 s2 = cadd(x3, x7), s3 = csub(x3, x7);                               \
    float2 O0 = cadd(s0, s2), O2 = csub(s0, s2);                               \
    float2 O1 = cadd(s1, mul_mi(s3)), O3 = cadd(s1, mul_pi(s3));               \
    float2 W1O = make_float2(C707 * (O1.x + O1.y), C707 * (O1.y - O1.x));      \
    float2 W2O = mul_mi(O2);                                                   \
    float2 W3O = make_float2(C707 * (O3.y - O3.x), -C707 * (O3.x + O3.y));     \
    X0 = cadd(E0, O0);  X4 = csub(E0, O0);                                     \
    X1 = cadd(E1, W1O); X5 = csub(E1, W1O);                                    \
    X2 = cadd(E2, W2O); X6 = csub(E2, W2O);                                    \
    X3 = cadd(E3, W3O); X7 = csub(E3, W3O);                                    \
} while (0)

// Register radix-8 + twiddle + scatter into dst.
#define STAGE8_STORE(dst, SL, t, r0,r1,r2,r3,r4,r5,r6,r7) do {                 \
    const int s_ = 1 << (SL);                                                  \
    float2 X0,X1,X2,X3,X4,X5,X6,X7;                                            \
    DFT8(r0,r1,r2,r3,r4,r5,r6,r7, X0,X1,X2,X3,X4,X5,X6,X7);                    \
    float th_ = (-(float)CUDART_PI / 1024.0f) * (float)((t) & ~(s_ - 1));      \
    float2 w1,w2,w3,w4;                                                        \
    __sincosf(th_,        &w1.y, &w1.x);                                       \
    __sincosf(2.0f * th_, &w2.y, &w2.x);                                       \
    __sincosf(3.0f * th_, &w3.y, &w3.x);                                       \
    __sincosf(4.0f * th_, &w4.y, &w4.x);                                       \
    float2 w5 = cmul(w1, w4), w6 = cmul(w2, w4), w7 = cmul(w3, w4);            \
    int ob_ = ((t) & (s_ - 1)) + (((t) >> (SL)) << ((SL) + 3));                \
    dst[F(ob_ + 0 * s_)] = X0;                                                 \
    dst[F(ob_ + 1 * s_)] = cmul(X1, w1);                                       \
    dst[F(ob_ + 2 * s_)] = cmul(X2, w2);                                       \
    dst[F(ob_ + 3 * s_)] = cmul(X3, w3);                                       \
    dst[F(ob_ + 4 * s_)] = cmul(X4, w4);                                       \
    dst[F(ob_ + 5 * s_)] = cmul(X5, w5);                                       \
    dst[F(ob_ + 6 * s_)] = cmul(X6, w6);                                       \
    dst[F(ob_ + 7 * s_)] = cmul(X7, w7);                                       \
} while (0)

#define LOAD256(src, t, r0,r1,r2,r3,r4,r5,r6,r7) do {                          \
    r0 = src[F((t) + 0 * 256)]; r1 = src[F((t) + 1 * 256)];                    \
    r2 = src[F((t) + 2 * 256)]; r3 = src[F((t) + 3 * 256)];                    \
    r4 = src[F((t) + 4 * 256)]; r5 = src[F((t) + 5 * 256)];                    \
    r6 = src[F((t) + 6 * 256)]; r7 = src[F((t) + 7 * 256)];                    \
} while (0)

__global__ __launch_bounds__(NT) void vpc_main(const float* __restrict__ x,
                                               const float* __restrict__ w,
                                               float* __restrict__ out) {
    __shared__ float2 sA[SPAD];
    __shared__ float2 sB[SPAD];

    const int tid = threadIdx.x;
    const int row = blockIdx.x;
    const float4* xr = (const float4*)(x + (size_t)row * N);
    const float4* w4p = (const float4*)w;

    float2 r0, r1, r2, r3, r4, r5, r6, r7;

    // ---- Head: z = exp(i*(x+w0)); pair butterfly fully in-thread.
    // Thread t handles x[8t .. 8t+7] (4 pairs), stores butterflied z to sA.
#pragma unroll
    for (int j = 0; j < 2; j++) {
        int q = 2 * tid + j;                 // float4 index
        float4 xv = xr[q];
        float4 wv = w4p[q];
        float s0, c0, s1, c1, s2, c2, s3, c3;
        __sincosf(xv.x + wv.x, &s0, &c0);
        __sincosf(xv.y + wv.y, &s1, &c1);
        __sincosf(xv.z + wv.z, &s2, &c2);
        __sincosf(xv.w + wv.w, &s3, &c3);
        int b = 4 * q;                        // element index 8t+4j
        sA[F(b + 0)] = make_float2(c0 + c1, s0 + s1);
        sA[F(b + 1)] = make_float2(c0 - c1, s0 - s1);
        sA[F(b + 2)] = make_float2(c2 + c3, s2 + s3);
        sA[F(b + 3)] = make_float2(c2 - c3, s2 - s3);
    }
    __syncthreads();

    // ---- FFT 2048 = 8*8*8*4 Stockham: 3 radix-8 stages (3 exchanges) ----
    LOAD256(sA, tid, r0, r1, r2, r3, r4, r5, r6, r7);
    STAGE8_STORE(sB, 0, tid, r0, r1, r2, r3, r4, r5, r6, r7);
    __syncthreads();
    LOAD256(sB, tid, r0, r1, r2, r3, r4, r5, r6, r7);
    STAGE8_STORE(sA, 3, tid, r0, r1, r2, r3, r4, r5, r6, r7);
    __syncthreads();
    LOAD256(sA, tid, r0, r1, r2, r3, r4, r5, r6, r7);
    STAGE8_STORE(sB, 6, tid, r0, r1, r2, r3, r4, r5, r6, r7);
    __syncthreads();

    // ---- Final radix-4 stage in registers; thread owns groups q=2t and 2t+1,
    //      i.e. BOTH elements of each pair n = 2t+512a, 2t+1+512a. ----
    float2 ue[4], uo[4];   // u' at even n=2t+512a, odd n=2t+1+512a (after cw1 mul)
    {
        float2 b0 = sB[F(2 * tid + 0 * 512)], b1 = sB[F(2 * tid + 1 * 512)];
        float2 b2 = sB[F(2 * tid + 2 * 512)], b3 = sB[F(2 * tid + 3 * 512)];
        float2 c0 = sB[F(2 * tid + 1 + 0 * 512)], c1 = sB[F(2 * tid + 1 + 1 * 512)];
        float2 c2 = sB[F(2 * tid + 1 + 2 * 512)], c3 = sB[F(2 * tid + 1 + 3 * 512)];
        float2 apc = cadd(b0, b2), amc = csub(b0, b2);
        float2 bpd = cadd(b1, b3), bmd = csub(b1, b3);
        ue[0] = cadd(apc, bpd);
        ue[1] = cadd(amc, mul_mi(bmd));
        ue[2] = csub(apc, bpd);
        ue[3] = cadd(amc, mul_pi(bmd));
        float2 epc = cadd(c0, c2), emc = csub(c0, c2);
        float2 fpd = cadd(c1, c3), fmd = csub(c1, c3);
        uo[0] = cadd(epc, fpd);
        uo[1] = cadd(emc, mul_mi(fmd));
        uo[2] = csub(epc, fpd);
        uo[3] = cadd(emc, mul_pi(fmd));
    }

    // ---- Layer 1 twiddle in registers: u' = u * exp(i*w1[n]) ----
    const float4* cw1_4 = (const float4*)g_cw1;
#pragma unroll
    for (int a = 0; a < 4; a++) {
        float4 cw = __ldg(&cw1_4[tid + 256 * a]);   // pair (2t+512a, 2t+1+512a)
        ue[a] = cmul(ue[a], make_float2(cw.x, cw.y));
        uo[a] = cmul(uo[a], make_float2(cw.z, cw.w));
    }

    // ---- Tail: X_k = sum_m W1024^{mk} (alpha_k u'_{2m} + beta_k u'_{2m+1}),
    //      m = t + 256a  ->  X_k = sum_t W1024^{tk} (alpha_k A_{k%4} + beta_k B_{k%4})
    //      with A_j = sum_a (-i)^{aj} ue[a], B_j likewise over uo. ----
    float2 A[4], B[4];
    {
        float2 p0 = cadd(ue[0], ue[2]), p1 = csub(ue[0], ue[2]);
        float2 p2 = cadd(ue[1], ue[3]), p3 = csub(ue[1], ue[3]);
        A[0] = cadd(p0, p2); A[2] = csub(p0, p2);
        A[1] = cadd(p1, mul_mi(p3)); A[3] = cadd(p1, mul_pi(p3));
        float2 q0 = cadd(uo[0], uo[2]), q1 = csub(uo[0], uo[2]);
        float2 q2 = cadd(uo[1], uo[3]), q3 = csub(uo[1], uo[3]);
        B[0] = cadd(q0, q2); B[2] = csub(q0, q2);
        B[1] = cadd(q1, mul_mi(q3)); B[3] = cadd(q1, mul_pi(q3));
    }

    float2 acc[NCLS];
    {
        float2 w1t;
        __sincosf((-2.0f * (float)CUDART_PI / 1024.0f) * (float)tid, &w1t.y, &w1t.x);
        float2 wk = make_float2(1.0f, 0.0f);
#pragma unroll
        for (int k = 0; k < NCLS; k++) {
            float sw, cw;
            __sincosf((-(float)CUDART_PI / 1024.0f) * (float)k, &sw, &cw);
            float2 al = make_float2(1.0f + cw, sw);
            float2 be = make_float2(1.0f - cw, -sw);
            float2 pre = cadd(cmul(al, A[k & 3]), cmul(be, B[k & 3]));
            acc[k] = cmul(wk, pre);
            wk = cmul(wk, w1t);
        }
    }

    // ---- Warp reduction ----
#pragma unroll
    for (int k = 0; k < NCLS; k++) {
#pragma unroll
        for (int off = 16; off > 0; off >>= 1) {
            acc[k].x += __shfl_down_sync(0xFFFFFFFFu, acc[k].x, off);
            acc[k].y += __shfl_down_sync(0xFFFFFFFFu, acc[k].y, off);
        }
    }

    // ---- Cross-warp reduction via sA (stage-3 sync already retired sA reads) ----
    float2* red   = sA;
    float* logits = (float*)(sA + 8 * NCLS);
    int lane = tid & 31, wrp = tid >> 5;
    if (lane == 0) {
#pragma unroll
        for (int k = 0; k < NCLS; k++) red[wrp * NCLS + k] = acc[k];
    }
    __syncthreads();

    if (tid < NCLS) {
        float re = 0.f, im = 0.f;
#pragma unroll
        for (int wq = 0; wq < NT / 32; wq++) {
            re += red[wq * NCLS + tid].x;
            im += red[wq * NCLS + tid].y;
        }
        float r2v = re * re + im * im;
        // sin(atan2(im,re)) = im/|z|; dropped norms are positive -> phases unchanged
        logits[tid] = (r2v > 0.f) ? 5.0f * im * rsqrtf(r2v) : 0.0f;
    }
    __syncthreads();

    if (tid < NCLS) {
        float m = -1e30f;
#pragma unroll
        for (int k = 0; k < NCLS; k++) m = fmaxf(m, logits[k]);
        float sum = 0.f;
#pragma unroll
        for (int k = 0; k < NCLS; k++) sum += expf(logits[k] - m);
        out[(size_t)row * NCLS + tid] = expf(logits[tid] - m) / sum;
    }
}

extern "C" void kernel_launch(void* const* d_in, const int* in_sizes, int n_in,
                              void* d_out, int out_size) {
    const float* x = (const float*)d_in[0];     // (8192, 2048) fp32
    const float* w = (const float*)d_in[1];     // (4096,) fp32
    float* out = (float*)d_out;                 // (8192, 10) fp32

    vpc_init<<<(N + 255) / 256, 256>>>(w);
    vpc_main<<<8192, NT>>>(x, w, out);
}

// round 5
// speedup vs baseline: 1.6667x; 1.1217x over previous
#include <cuda_runtime.h>
#include <math_constants.h>

#define N     2048
#define NT    256
#define NCLS  10
#define C707  0.70710678118654752440f

// pad mapping: 2 extra float2 per 16 -> conflict-free for stride 1/8/64/256
// patterns AND keeps 16-byte alignment of even-indexed elements.
#define F(i) ((i) + (((i) >> 4) << 1))
#define SPAD 2304

__device__ float2 g_cw1[N];   // exp(i*w1[n]), row-invariant

__global__ void vpc_init(const float* __restrict__ w) {
    int i = blockIdx.x * blockDim.x + threadIdx.x;
    if (i < N) {
        float s, c;
        sincosf(w[N + i], &s, &c);
        g_cw1[i] = make_float2(c, s);
    }
}

__device__ __forceinline__ float2 cmul(float2 a, float2 b) {
    return make_float2(a.x * b.x - a.y * b.y, a.x * b.y + a.y * b.x);
}
__device__ __forceinline__ float2 cadd(float2 a, float2 b) { return make_float2(a.x + b.x, a.y + b.y); }
__device__ __forceinline__ float2 csub(float2 a, float2 b) { return make_float2(a.x - b.x, a.y - b.y); }
__device__ __forceinline__ float2 mul_mi(float2 z) { return make_float2(z.y, -z.x); }   // z * (-i)
__device__ __forceinline__ float2 mul_pi(float2 z) { return make_float2(-z.y, z.x); }   // z * (+i)

// DFT8 (forward, W8 = e^{-i pi/4})
#define DFT8(x0,x1,x2,x3,x4,x5,x6,x7, X0,X1,X2,X3,X4,X5,X6,X7) do {            \
    float2 t0 = cadd(x0, x4), t1 = csub(x0, x4);                               \
    float2 t2 = cadd(x2, x6), t3 = csub(x2, x6);                               \
    float2 E0 = cadd(t0, t2), E2 = csub(t0, t2);                               \
    float2 E1 = cadd(t1, mul_mi(t3)), E3 = cadd(t1, mul_pi(t3));               \
    float2 s0 = cadd(x1, x5), s1 = csub(x1, x5);                               \
    float2 s2 = cadd(x3, x7), s3 = csub(x3, x7);                               \
    float2 O0 = cadd(s0, s2), O2 = csub(s0, s2);                               \
    float2 O1 = cadd(s1, mul_mi(s3)), O3 = cadd(s1, mul_pi(s3));               \
    float2 W1O = make_float2(C707 * (O1.x + O1.y), C707 * (O1.y - O1.x));      \
    float2 W2O = mul_mi(O2);                                                   \
    float2 W3O = make_float2(C707 * (O3.y - O3.x), -C707 * (O3.x + O3.y));     \
    X0 = cadd(E0, O0);  X4 = csub(E0, O0);                                     \
    X1 = cadd(E1, W1O); X5 = csub(E1, W1O);                                    \
    X2 = cadd(E2, W2O); X6 = csub(E2, W2O);                                    \
    X3 = cadd(E3, W3O); X7 = csub(E3, W3O);                                    \
} while (0)

// One Stockham radix-8 stage: gather stride-256, register DFT8,
// twiddle via power chain (1 sincos), scatter (vectorized when SL==0).
template <int SL>
__device__ __forceinline__ void stage8(const float2* __restrict__ src,
                                       float2* __restrict__ dst, int t) {
    const int s = 1 << SL;
    float2 r0 = src[F(t + 0 * 256)], r1 = src[F(t + 1 * 256)];
    float2 r2 = src[F(t + 2 * 256)], r3 = src[F(t + 3 * 256)];
    float2 r4 = src[F(t + 4 * 256)], r5 = src[F(t + 5 * 256)];
    float2 r6 = src[F(t + 6 * 256)], r7 = src[F(t + 7 * 256)];
    float2 X0, X1, X2, X3, X4, X5, X6, X7;
    DFT8(r0, r1, r2, r3, r4, r5, r6, r7, X0, X1, X2, X3, X4, X5, X6, X7);

    float th = (-(float)CUDART_PI / 1024.0f) * (float)(t & ~(s - 1));
    float2 w1;
    __sincosf(th, &w1.y, &w1.x);
    float2 w2 = cmul(w1, w1);
    float2 w3 = cmul(w1, w2);
    float2 w4 = cmul(w2, w2);
    float2 w5 = cmul(w1, w4);
    float2 w6 = cmul(w2, w4);
    float2 w7 = cmul(w3, w4);
    X1 = cmul(X1, w1); X2 = cmul(X2, w2); X3 = cmul(X3, w3); X4 = cmul(X4, w4);
    X5 = cmul(X5, w5); X6 = cmul(X6, w6); X7 = cmul(X7, w7);

    if (SL == 0) {
        // ob = 8t, 8 contiguous float2, 16B-aligned under F -> 4x STS.128
        float4* d4 = (float4*)(dst + F(8 * t));
        d4[0] = make_float4(X0.x, X0.y, X1.x, X1.y);
        d4[1] = make_float4(X2.x, X2.y, X3.x, X3.y);
        d4[2] = make_float4(X4.x, X4.y, X5.x, X5.y);
        d4[3] = make_float4(X6.x, X6.y, X7.x, X7.y);
    } else {
        int ob = (t & (s - 1)) + ((t >> SL) << (SL + 3));
        dst[F(ob + 0 * s)] = X0;
        dst[F(ob + 1 * s)] = X1;
        dst[F(ob + 2 * s)] = X2;
        dst[F(ob + 3 * s)] = X3;
        dst[F(ob + 4 * s)] = X4;
        dst[F(ob + 5 * s)] = X5;
        dst[F(ob + 6 * s)] = X6;
        dst[F(ob + 7 * s)] = X7;
    }
}

__global__ __launch_bounds__(NT) void vpc_main(const float* __restrict__ x,
                                               const float* __restrict__ w,
                                               float* __restrict__ out) {
    __shared__ float2 sA[SPAD];
    __shared__ float2 sB[SPAD];

    const int tid = threadIdx.x;
    const int row = blockIdx.x;
    const float4* xr  = (const float4*)(x + (size_t)row * N);
    const float4* w4p = (const float4*)w;

    // ---- Head: z = exp(i*(x+w0)); pair butterfly in-thread, vector store ----
#pragma unroll
    for (int j = 0; j < 2; j++) {
        int q = 2 * tid + j;                 // float4 index
        float4 xv = xr[q];
        float4 wv = w4p[q];
        float s0, c0, s1, c1, s2, c2, s3, c3;
        __sincosf(xv.x + wv.x, &s0, &c0);
        __sincosf(xv.y + wv.y, &s1, &c1);
        __sincosf(xv.z + wv.z, &s2, &c2);
        __sincosf(xv.w + wv.w, &s3, &c3);
        float4* d4 = (float4*)(sA + F(4 * q));   // 4 contiguous float2, aligned
        d4[0] = make_float4(c0 + c1, s0 + s1, c0 - c1, s0 - s1);
        d4[1] = make_float4(c2 + c3, s2 + s3, c2 - c3, s2 - s3);
    }
    __syncthreads();

    // ---- FFT 2048 = 8*8*8*4 Stockham: 3 radix-8 stages ----
    stage8<0>(sA, sB, tid); __syncthreads();
    stage8<3>(sB, sA, tid); __syncthreads();
    stage8<6>(sA, sB, tid); __syncthreads();

    // ---- Final radix-4 in registers; thread owns pairs n=2t+512a, 2t+1+512a ----
    float2 ue[4], uo[4];
    {
        float4 p0 = *(const float4*)(sB + F(2 * tid + 0 * 512));
        float4 p1 = *(const float4*)(sB + F(2 * tid + 1 * 512));
        float4 p2 = *(const float4*)(sB + F(2 * tid + 2 * 512));
        float4 p3 = *(const float4*)(sB + F(2 * tid + 3 * 512));
        float2 b0 = make_float2(p0.x, p0.y), c0 = make_float2(p0.z, p0.w);
        float2 b1 = make_float2(p1.x, p1.y), c1 = make_float2(p1.z, p1.w);
        float2 b2 = make_float2(p2.x, p2.y), c2 = make_float2(p2.z, p2.w);
        float2 b3 = make_float2(p3.x, p3.y), c3 = make_float2(p3.z, p3.w);
        float2 apc = cadd(b0, b2), amc = csub(b0, b2);
        float2 bpd = cadd(b1, b3), bmd = csub(b1, b3);
        ue[0] = cadd(apc, bpd);
        ue[1] = cadd(amc, mul_mi(bmd));
        ue[2] = csub(apc, bpd);
        ue[3] = cadd(amc, mul_pi(bmd));
        float2 epc = cadd(c0, c2), emc = csub(c0, c2);
        float2 fpd = cadd(c1, c3), fmd = csub(c1, c3);
        uo[0] = cadd(epc, fpd);
        uo[1] = cadd(emc, mul_mi(fmd));
        uo[2] = csub(epc, fpd);
        uo[3] = cadd(emc, mul_pi(fmd));
    }

    // ---- Layer 1 twiddle in registers ----
    const float4* cw1_4 = (const float4*)g_cw1;
#pragma unroll
    for (int a = 0; a < 4; a++) {
        float4 cw = __ldg(&cw1_4[tid + 256 * a]);
        ue[a] = cmul(ue[a], make_float2(cw.x, cw.y));
        uo[a] = cmul(uo[a], make_float2(cw.z, cw.w));
    }

    // ---- Tail: X_k = sum_t W1024^{tk} (alpha_k A_{k%4} + beta_k B_{k%4}) ----
    float2 A[4], B[4];
    {
        float2 p0 = cadd(ue[0], ue[2]), p1 = csub(ue[0], ue[2]);
        float2 p2 = cadd(ue[1], ue[3]), p3 = csub(ue[1], ue[3]);
        A[0] = cadd(p0, p2); A[2] = csub(p0, p2);
        A[1] = cadd(p1, mul_mi(p3)); A[3] = cadd(p1, mul_pi(p3));
        float2 q0 = cadd(uo[0], uo[2]), q1 = csub(uo[0], uo[2]);
        float2 q2 = cadd(uo[1], uo[3]), q3 = csub(uo[1], uo[3]);
        B[0] = cadd(q0, q2); B[2] = csub(q0, q2);
        B[1] = cadd(q1, mul_mi(q3)); B[3] = cadd(q1, mul_pi(q3));
    }

    // cos/sin(pi*k/1024), k=0..9 — compile-time constants
    const float CK[NCLS] = {1.0f, 0.99999529380957619f, 0.99998117528260111f,
                            0.99995764455196390f, 0.99992470183914450f,
                            0.99988234745421256f, 0.99983058179582340f,
                            0.99976940535121528f, 0.99969881869620425f,
                            0.99961882249517864f};
    const float SK[NCLS] = {0.0f, 0.0030679567629659761f, 0.0061358846491544753f,
                            0.0092037547820598194f, 0.012271538285719925f,
                            0.015339206284988100f, 0.018406729905804820f,
                            0.021474080275469508f, 0.024541228522912288f,
                            0.027608145778965740f};

    float2 acc[NCLS];
    {
        float2 w1t;
        __sincosf((-2.0f * (float)CUDART_PI / 1024.0f) * (float)tid, &w1t.y, &w1t.x);
        float2 wk = make_float2(1.0f, 0.0f);
#pragma unroll
        for (int k = 0; k < NCLS; k++) {
            float2 al = make_float2(1.0f + CK[k], -SK[k]);
            float2 be = make_float2(1.0f - CK[k],  SK[k]);
            float2 pre = cadd(cmul(al, A[k & 3]), cmul(be, B[k & 3]));
            acc[k] = cmul(wk, pre);
            wk = cmul(wk, w1t);
        }
    }

    // ---- Warp reduction ----
#pragma unroll
    for (int k = 0; k < NCLS; k++) {
#pragma unroll
        for (int off = 16; off > 0; off >>= 1) {
            acc[k].x += __shfl_down_sync(0xFFFFFFFFu, acc[k].x, off);
            acc[k].y += __shfl_down_sync(0xFFFFFFFFu, acc[k].y, off);
        }
    }

    // ---- Cross-warp reduction via sA ----
    float2* red   = sA;
    float* logits = (float*)(sA + 8 * NCLS);
    int lane = tid & 31, wrp = tid >> 5;
    if (lane == 0) {
#pragma unroll
        for (int k = 0; k < NCLS; k++) red[wrp * NCLS + k] = acc[k];
    }
    __syncthreads();

    if (tid < NCLS) {
        float re = 0.f, im = 0.f;
#pragma unroll
        for (int wq = 0; wq < NT / 32; wq++) {
            re += red[wq * NCLS + tid].x;
            im += red[wq * NCLS + tid].y;
        }
        float r2v = re * re + im * im;
        // sin(atan2(im,re)) = im/|z|; dropped norms are positive -> phases unchanged
        logits[tid] = (r2v > 0.f) ? 5.0f * im * rsqrtf(r2v) : 0.0f;
    }
    __syncthreads();

    if (tid < NCLS) {
        float m = -1e30f;
#pragma unroll
        for (int k = 0; k < NCLS; k++) m = fmaxf(m, logits[k]);
        float sum = 0.f;
#pragma unroll
        for (int k = 0; k < NCLS; k++) sum += expf(logits[k] - m);
        out[(size_t)row * NCLS + tid] = expf(logits[tid] - m) / sum;
    }
}

extern "C" void kernel_launch(void* const* d_in, const int* in_sizes, int n_in,
                              void* d_out, int out_size) {
    const float* x = (const float*)d_in[0];     // (8192, 2048) fp32
    const float* w = (const float*)d_in[1];     // (4096,) fp32
    float* out = (float*)d_out;                 // (8192, 10) fp32

    vpc_init<<<(N + 255) / 256, 256>>>(w);
    vpc_main<<<8192, NT>>>(x, w, out);
}

// round 6
// speedup vs baseline: 1.9802x; 1.1881x over previous
#include <cuda_runtime.h>
#include <math_constants.h>

#define N     2048
#define NT    256
#define NCLS  10
#define C707  0.70710678118654752440f

// pad mapping: 2 extra float2 per 16 -> conflict-free for stride 1/8/64/256
// patterns AND keeps 16-byte alignment of even-indexed elements.
#define F(i) ((i) + (((i) >> 4) << 1))
#define SPAD 2304

__device__ float2 g_cw1[N];   // exp(i*w1[n]), row-invariant

__global__ void vpc_init(const float* __restrict__ w) {
    int i = blockIdx.x * blockDim.x + threadIdx.x;
    if (i < N) {
        float s, c;
        sincosf(w[N + i], &s, &c);
        g_cw1[i] = make_float2(c, s);
    }
}

__device__ __forceinline__ float2 cmul(float2 a, float2 b) {
    return make_float2(a.x * b.x - a.y * b.y, a.x * b.y + a.y * b.x);
}
__device__ __forceinline__ float2 cadd(float2 a, float2 b) { return make_float2(a.x + b.x, a.y + b.y); }
__device__ __forceinline__ float2 csub(float2 a, float2 b) { return make_float2(a.x - b.x, a.y - b.y); }
__device__ __forceinline__ float2 mul_mi(float2 z) { return make_float2(z.y, -z.x); }   // z * (-i)
__device__ __forceinline__ float2 mul_pi(float2 z) { return make_float2(-z.y, z.x); }   // z * (+i)

// DFT8 (forward, W8 = e^{-i pi/4})
#define DFT8(x0,x1,x2,x3,x4,x5,x6,x7, X0,X1,X2,X3,X4,X5,X6,X7) do {            \
    float2 t0 = cadd(x0, x4), t1 = csub(x0, x4);                               \
    float2 t2 = cadd(x2, x6), t3 = csub(x2, x6);                               \
    float2 E0 = cadd(t0, t2), E2 = csub(t0, t2);                               \
    float2 E1 = cadd(t1, mul_mi(t3)), E3 = cadd(t1, mul_pi(t3));               \
    float2 s0 = cadd(x1, x5), s1 = csub(x1, x5);                               \
    float2 s2 = cadd(x3, x7), s3 = csub(x3, x7);                               \
    float2 O0 = cadd(s0, s2), O2 = csub(s0, s2);                               \
    float2 O1 = cadd(s1, mul_mi(s3)), O3 = cadd(s1, mul_pi(s3));               \
    float2 W1O = make_float2(C707 * (O1.x + O1.y), C707 * (O1.y - O1.x));      \
    float2 W2O = mul_mi(O2);                                                   \
    float2 W3O = make_float2(C707 * (O3.y - O3.x), -C707 * (O3.x + O3.y));     \
    X0 = cadd(E0, O0);  X4 = csub(E0, O0);                                     \
    X1 = cadd(E1, W1O); X5 = csub(E1, W1O);                                    \
    X2 = cadd(E2, W2O); X6 = csub(E2, W2O);                                    \
    X3 = cadd(E3, W3O); X7 = csub(E3, W3O);                                    \
} while (0)

// One Stockham radix-8 stage.
template <int SL>
__device__ __forceinline__ void stage8(const float2* __restrict__ src,
                                       float2* __restrict__ dst, int t) {
    const int s = 1 << SL;
    float2 r0 = src[F(t + 0 * 256)], r1 = src[F(t + 1 * 256)];
    float2 r2 = src[F(t + 2 * 256)], r3 = src[F(t + 3 * 256)];
    float2 r4 = src[F(t + 4 * 256)], r5 = src[F(t + 5 * 256)];
    float2 r6 = src[F(t + 6 * 256)], r7 = src[F(t + 7 * 256)];
    float2 X0, X1, X2, X3, X4, X5, X6, X7;
    DFT8(r0, r1, r2, r3, r4, r5, r6, r7, X0, X1, X2, X3, X4, X5, X6, X7);

    float th = (-(float)CUDART_PI / 1024.0f) * (float)(t & ~(s - 1));
    float2 w1;
    __sincosf(th, &w1.y, &w1.x);
    float2 w2 = cmul(w1, w1);
    float2 w3 = cmul(w1, w2);
    float2 w4 = cmul(w2, w2);
    float2 w5 = cmul(w1, w4);
    float2 w6 = cmul(w2, w4);
    float2 w7 = cmul(w3, w4);
    X1 = cmul(X1, w1); X2 = cmul(X2, w2); X3 = cmul(X3, w3); X4 = cmul(X4, w4);
    X5 = cmul(X5, w5); X6 = cmul(X6, w6); X7 = cmul(X7, w7);

    if (SL == 0) {
        float4* d4 = (float4*)(dst + F(8 * t));
        d4[0] = make_float4(X0.x, X0.y, X1.x, X1.y);
        d4[1] = make_float4(X2.x, X2.y, X3.x, X3.y);
        d4[2] = make_float4(X4.x, X4.y, X5.x, X5.y);
        d4[3] = make_float4(X6.x, X6.y, X7.x, X7.y);
    } else {
        int ob = (t & (s - 1)) + ((t >> SL) << (SL + 3));
        dst[F(ob + 0 * s)] = X0;
        dst[F(ob + 1 * s)] = X1;
        dst[F(ob + 2 * s)] = X2;
        dst[F(ob + 3 * s)] = X3;
        dst[F(ob + 4 * s)] = X4;
        dst[F(ob + 5 * s)] = X5;
        dst[F(ob + 6 * s)] = X6;
        dst[F(ob + 7 * s)] = X7;
    }
}

__global__ __launch_bounds__(NT) void vpc_main(const float* __restrict__ x,
                                               const float* __restrict__ w,
                                               float* __restrict__ out) {
    __shared__ float2 sA[SPAD];
    __shared__ float2 sB[SPAD];

    const int tid = threadIdx.x;
    const int row = blockIdx.x;
    const float4* xr  = (const float4*)(x + (size_t)row * N);
    const float4* w4p = (const float4*)w;

    // ---- Head: z = exp(i*(x+w0)); pair butterfly in-thread, vector store ----
#pragma unroll
    for (int j = 0; j < 2; j++) {
        int q = 2 * tid + j;
        float4 xv = xr[q];
        float4 wv = w4p[q];
        float s0, c0, s1, c1, s2, c2, s3, c3;
        __sincosf(xv.x + wv.x, &s0, &c0);
        __sincosf(xv.y + wv.y, &s1, &c1);
        __sincosf(xv.z + wv.z, &s2, &c2);
        __sincosf(xv.w + wv.w, &s3, &c3);
        float4* d4 = (float4*)(sA + F(4 * q));
        d4[0] = make_float4(c0 + c1, s0 + s1, c0 - c1, s0 - s1);
        d4[1] = make_float4(c2 + c3, s2 + s3, c2 - c3, s2 - s3);
    }
    __syncthreads();

    // ---- FFT 2048 = 8*8*8*4 Stockham: 3 radix-8 stages ----
    stage8<0>(sA, sB, tid); __syncthreads();
    stage8<3>(sB, sA, tid); __syncthreads();
    stage8<6>(sA, sB, tid); __syncthreads();

    // ---- Final radix-4 in registers; thread owns pairs n=2t+512a, 2t+1+512a ----
    float2 ue[4], uo[4];
    {
        float4 p0 = *(const float4*)(sB + F(2 * tid + 0 * 512));
        float4 p1 = *(const float4*)(sB + F(2 * tid + 1 * 512));
        float4 p2 = *(const float4*)(sB + F(2 * tid + 2 * 512));
        float4 p3 = *(const float4*)(sB + F(2 * tid + 3 * 512));
        float2 b0 = make_float2(p0.x, p0.y), c0 = make_float2(p0.z, p0.w);
        float2 b1 = make_float2(p1.x, p1.y), c1 = make_float2(p1.z, p1.w);
        float2 b2 = make_float2(p2.x, p2.y), c2 = make_float2(p2.z, p2.w);
        float2 b3 = make_float2(p3.x, p3.y), c3 = make_float2(p3.z, p3.w);
        float2 apc = cadd(b0, b2), amc = csub(b0, b2);
        float2 bpd = cadd(b1, b3), bmd = csub(b1, b3);
        ue[0] = cadd(apc, bpd);
        ue[1] = cadd(amc, mul_mi(bmd));
        ue[2] = csub(apc, bpd);
        ue[3] = cadd(amc, mul_pi(bmd));
        float2 epc = cadd(c0, c2), emc = csub(c0, c2);
        float2 fpd = cadd(c1, c3), fmd = csub(c1, c3);
        uo[0] = cadd(epc, fpd);
        uo[1] = cadd(emc, mul_mi(fmd));
        uo[2] = csub(epc, fpd);
        uo[3] = cadd(emc, mul_pi(fmd));
    }

    // ---- Layer 1 twiddle in registers ----
    const float4* cw1_4 = (const float4*)g_cw1;
#pragma unroll
    for (int a = 0; a < 4; a++) {
        float4 cw = __ldg(&cw1_4[tid + 256 * a]);
        ue[a] = cmul(ue[a], make_float2(cw.x, cw.y));
        uo[a] = cmul(uo[a], make_float2(cw.z, cw.w));
    }

    // ---- Tail: X_k = sum_t W1024^{tk} (alpha_k A_{k%4} + beta_k B_{k%4}) ----
    float2 A[4], B[4];
    {
        float2 p0 = cadd(ue[0], ue[2]), p1 = csub(ue[0], ue[2]);
        float2 p2 = cadd(ue[1], ue[3]), p3 = csub(ue[1], ue[3]);
        A[0] = cadd(p0, p2); A[2] = csub(p0, p2);
        A[1] = cadd(p1, mul_mi(p3)); A[3] = cadd(p1, mul_pi(p3));
        float2 q0 = cadd(uo[0], uo[2]), q1 = csub(uo[0], uo[2]);
        float2 q2 = cadd(uo[1], uo[3]), q3 = csub(uo[1], uo[3]);
        B[0] = cadd(q0, q2); B[2] = csub(q0, q2);
        B[1] = cadd(q1, mul_mi(q3)); B[3] = cadd(q1, mul_pi(q3));
    }

    // cos/sin(pi*k/1024), k=0..9 — compile-time constants
    const float CK[NCLS] = {1.0f, 0.99999529380957619f, 0.99998117528260111f,
                            0.99995764455196390f, 0.99992470183914450f,
                            0.99988234745421256f, 0.99983058179582340f,
                            0.99976940535121528f, 0.99969881869620425f,
                            0.99961882249517864f};
    const float SK[NCLS] = {0.0f, 0.0030679567629659761f, 0.0061358846491544753f,
                            0.0092037547820598194f, 0.012271538285719925f,
                            0.015339206284988100f, 0.018406729905804820f,
                            0.021474080275469508f, 0.024541228522912288f,
                            0.027608145778965740f};

    // v[20]: v[2k]=Re X_k, v[2k+1]=Im X_k (per-thread partial)
    float v[20];
    {
        float2 w1t;
        __sincosf((-2.0f * (float)CUDART_PI / 1024.0f) * (float)tid, &w1t.y, &w1t.x);
        float2 wk = make_float2(1.0f, 0.0f);
#pragma unroll
        for (int k = 0; k < NCLS; k++) {
            float2 al = make_float2(1.0f + CK[k], -SK[k]);
            float2 be = make_float2(1.0f - CK[k],  SK[k]);
            float2 pre = cadd(cmul(al, A[k & 3]), cmul(be, B[k & 3]));
            float2 ac = cmul(wk, pre);
            v[2 * k] = ac.x; v[2 * k + 1] = ac.y;
            wk = cmul(wk, w1t);
        }
    }

    // ---- Value-splitting warp reduction: 20 scalars -> 5 per lane ----
    const int lane = tid & 31;
    // level 1 (xor 16): keep half of 20 -> 10
    float h1[10];
    {
        const bool hi = (lane & 16);
#pragma unroll
        for (int j = 0; j < 10; j++) {
            float send = hi ? v[j] : v[j + 10];
            float recv = __shfl_xor_sync(0xFFFFFFFFu, send, 16);
            h1[j] = (hi ? v[j + 10] : v[j]) + recv;
        }
    }
    // level 2 (xor 8): 10 -> 5
    float h2[5];
    {
        const bool hi = (lane & 8);
#pragma unroll
        for (int j = 0; j < 5; j++) {
            float send = hi ? h1[j] : h1[j + 5];
            float recv = __shfl_xor_sync(0xFFFFFFFFu, send, 8);
            h2[j] = (hi ? h1[j + 5] : h1[j]) + recv;
        }
    }
    // levels 3-5 (xor 4,2,1): plain butterflies on 5 scalars
#pragma unroll
    for (int off = 4; off > 0; off >>= 1) {
#pragma unroll
        for (int j = 0; j < 5; j++)
            h2[j] += __shfl_xor_sync(0xFFFFFFFFu, h2[j], off);
    }
    // lane L (L%8==0) holds scalars [5q..5q+4], q = (L>>3)&3

    // ---- Cross-warp reduction via sA ----
    float* red    = (float*)sA;                 // 8 warps * 20 scalars
    float* logits = (float*)sA + 8 * 20;
    const int wrp = tid >> 5;
    if ((lane & 7) == 0) {
        int base = wrp * 20 + ((lane >> 3) & 3) * 5;
#pragma unroll
        for (int j = 0; j < 5; j++) red[base + j] = h2[j];
    }
    __syncthreads();

    if (tid < NCLS) {
        float re = 0.f, im = 0.f;
#pragma unroll
        for (int wq = 0; wq < NT / 32; wq++) {
            re += red[wq * 20 + 2 * tid];
            im += red[wq * 20 + 2 * tid + 1];
        }
        float r2v = re * re + im * im;
        // sin(atan2(im,re)) = im/|z|; dropped norms are positive -> phases unchanged
        logits[tid] = (r2v > 0.f) ? 5.0f * im * rsqrtf(r2v) : 0.0f;
    }
    __syncthreads();

    if (tid < NCLS) {
        float m = -1e30f;
#pragma unroll
        for (int k = 0; k < NCLS; k++) m = fmaxf(m, logits[k]);
        float sum = 0.f;
#pragma unroll
        for (int k = 0; k < NCLS; k++) sum += __expf(logits[k] - m);
        out[(size_t)row * NCLS + tid] = __expf(logits[tid] - m) / sum;
    }
}

extern "C" void kernel_launch(void* const* d_in, const int* in_sizes, int n_in,
                              void* d_out, int out_size) {
    const float* x = (const float*)d_in[0];     // (8192, 2048) fp32
    const float* w = (const float*)d_in[1];     // (4096,) fp32
    float* out = (float*)d_out;                 // (8192, 10) fp32

    vpc_init<<<(N + 255) / 256, 256>>>(w);
    vpc_main<<<8192, NT>>>(x, w, out);
}

// round 7
// speedup vs baseline: 2.0175x; 1.0188x over previous
#include <cuda_runtime.h>
#include <math_constants.h>

#define N     2048
#define NT    256
#define NCLS  10
#define C707  0.70710678118654752440f

// pad mapping: 2 extra float2 per 16 -> conflict-free for stride 1/8/64/256
// patterns AND keeps 16-byte alignment of even-indexed elements.
#define F(i) ((i) + (((i) >> 4) << 1))
#define SPAD 2304

typedef unsigned long long ull;

__device__ float2 g_cw1[N];   // exp(i*w1[n]), row-invariant

__global__ void vpc_init(const float* __restrict__ w) {
    int i = blockIdx.x * blockDim.x + threadIdx.x;
    if (i < N) {
        float s, c;
        sincosf(w[N + i], &s, &c);
        g_cw1[i] = make_float2(c, s);
    }
}

// ---- packed f32x2 helpers (complex held as ull: lo=re, hi=im) ----
__device__ __forceinline__ ull pk2(float x, float y) {
    ull r; asm("mov.b64 %0,{%1,%2};" : "=l"(r) : "f"(x), "f"(y)); return r;
}
__device__ __forceinline__ void up2(ull z, float& x, float& y) {
    asm("mov.b64 {%0,%1},%2;" : "=f"(x), "=f"(y) : "l"(z));
}
__device__ __forceinline__ ull padd(ull a, ull b) {
    ull d; asm("add.rn.f32x2 %0,%1,%2;" : "=l"(d) : "l"(a), "l"(b)); return d;
}
__device__ __forceinline__ ull psub(ull a, ull b) {
    ull d; asm("sub.rn.f32x2 %0,%1,%2;" : "=l"(d) : "l"(a), "l"(b)); return d;
}
__device__ __forceinline__ ull pmul(ull a, ull b) {
    ull d; asm("mul.rn.f32x2 %0,%1,%2;" : "=l"(d) : "l"(a), "l"(b)); return d;
}
// z * (-i) = (im, -re)
__device__ __forceinline__ ull pmi(ull z) {
    float x, y; up2(z, x, y); return pk2(y, -x);
}

// Packed DFT8 (forward, W8 = e^{-i pi/4}); C707P = pk2(C707, C707)
#define DFT8P(x0,x1,x2,x3,x4,x5,x6,x7, X0,X1,X2,X3,X4,X5,X6,X7) do {           \
    ull t0 = padd(x0, x4), t1 = psub(x0, x4);                                  \
    ull t2 = padd(x2, x6), t3 = psub(x2, x6);                                  \
    ull E0 = padd(t0, t2), E2 = psub(t0, t2);                                  \
    ull m3 = pmi(t3);                                                          \
    ull E1 = padd(t1, m3), E3 = psub(t1, m3);                                  \
    ull s0 = padd(x1, x5), s1 = psub(x1, x5);                                  \
    ull s2 = padd(x3, x7), s3 = psub(x3, x7);                                  \
    ull O0 = padd(s0, s2), O2 = psub(s0, s2);                                  \
    ull n3 = pmi(s3);                                                          \
    ull O1 = padd(s1, n3), O3 = psub(s1, n3);                                  \
    ull W1O = pmul(C707P, padd(O1, pmi(O1)));                                  \
    ull W2O = pmi(O2);                                                         \
    ull W3O = pmul(C707P, psub(pmi(O3), O3));                                  \
    X0 = padd(E0, O0);  X4 = psub(E0, O0);                                     \
    X1 = padd(E1, W1O); X5 = psub(E1, W1O);                                    \
    X2 = padd(E2, W2O); X6 = psub(E2, W2O);                                    \
    X3 = padd(E3, W3O); X7 = psub(E3, W3O);                                    \
} while (0)

// One Stockham radix-8 stage, packed data path.
// SL==0: twbase = tw1 table (indexed by t), twiddles via power chain; returns w1.
// SL>0 : twbase = per-thread 7-entry twiddle base.
template <int SL>
__device__ __forceinline__ float2 stage8p(const float2* __restrict__ src,
                                          float2* __restrict__ dst, int t,
                                          const float2* __restrict__ twbase,
                                          const ull C707P) {
    const int s = 1 << SL;
    const ull* S = (const ull*)src;
    ull a0 = S[F(t + 0 * 256)], a1 = S[F(t + 1 * 256)];
    ull a2 = S[F(t + 2 * 256)], a3 = S[F(t + 3 * 256)];
    ull a4 = S[F(t + 4 * 256)], a5 = S[F(t + 5 * 256)];
    ull a6 = S[F(t + 6 * 256)], a7 = S[F(t + 7 * 256)];
    ull X0, X1, X2, X3, X4, X5, X6, X7;
    DFT8P(a0, a1, a2, a3, a4, a5, a6, a7, X0, X1, X2, X3, X4, X5, X6, X7);

    float wr1, wi1, wr2, wi2, wr3, wi3, wr4, wi4, wr5, wi5, wr6, wi6, wr7, wi7;
    float2 w1ret;
    if (SL == 0) {
        float2 w1 = twbase[t];
        w1ret = w1;
        wr1 = w1.x; wi1 = w1.y;
        wr2 = wr1 * wr1 - wi1 * wi1;  wi2 = 2.0f * wr1 * wi1;
        wr3 = wr1 * wr2 - wi1 * wi2;  wi3 = wr1 * wi2 + wi1 * wr2;
        wr4 = wr2 * wr2 - wi2 * wi2;  wi4 = 2.0f * wr2 * wi2;
        wr5 = wr1 * wr4 - wi1 * wi4;  wi5 = wr1 * wi4 + wi1 * wr4;
        wr6 = wr2 * wr4 - wi2 * wi4;  wi6 = wr2 * wi4 + wi2 * wr4;
        wr7 = wr3 * wr4 - wi3 * wi4;  wi7 = wr3 * wi4 + wi3 * wr4;
    } else {
        float2 v1 = twbase[0], v2 = twbase[1], v3 = twbase[2], v4 = twbase[3];
        float2 v5 = twbase[4], v6 = twbase[5], v7 = twbase[6];
        wr1 = v1.x; wi1 = v1.y; wr2 = v2.x; wi2 = v2.y; wr3 = v3.x; wi3 = v3.y;
        wr4 = v4.x; wi4 = v4.y; wr5 = v5.x; wi5 = v5.y; wr6 = v6.x; wi6 = v6.y;
        wr7 = v7.x; wi7 = v7.y;
        w1ret = v1;
    }

    int ob = (t & (s - 1)) + ((t >> SL) << (SL + 3));
    ((ull*)dst)[F(ob)] = X0;
#define APPL(XJ, J, WR, WI) do {                                               \
        float xr_, xi_; up2(XJ, xr_, xi_);                                     \
        dst[F(ob + (J) * s)] =                                                 \
            make_float2(xr_ * (WR) - xi_ * (WI), xr_ * (WI) + xi_ * (WR));     \
    } while (0)
    APPL(X1, 1, wr1, wi1); APPL(X2, 2, wr2, wi2); APPL(X3, 3, wr3, wi3);
    APPL(X4, 4, wr4, wi4); APPL(X5, 5, wr5, wi5); APPL(X6, 6, wr6, wi6);
    APPL(X7, 7, wr7, wi7);
#undef APPL
    return w1ret;
}

__global__ __launch_bounds__(NT, 5) void vpc_main(const float* __restrict__ x,
                                                  const float* __restrict__ w,
                                                  float* __restrict__ out) {
    __shared__ float2 sA[SPAD];
    __shared__ float2 sB[SPAD];
    __shared__ float2 sT[512];   // [0:256) tw1, [256:480) tw2, [480:508) tw3

    const int tid = threadIdx.x;
    const int row = blockIdx.x;
    const float4* xr  = (const float4*)(x + (size_t)row * N);
    const float4* w4p = (const float4*)w;
    const ull C707P = pk2(C707, C707);

    // ---- Twiddle table fill (once per CTA, overlapped with head) ----
    {
        float s, c;
        __sincosf((-(float)CUDART_PI / 1024.0f) * (float)tid, &s, &c);
        sT[tid] = make_float2(c, s);
        if (tid < 224) {                       // stage2: p=0..31, j=1..7
            int p = tid / 7, j = tid - p * 7 + 1;
            float s2, c2;
            __sincosf((-(float)CUDART_PI / 128.0f) * (float)(p * j), &s2, &c2);
            sT[256 + tid] = make_float2(c2, s2);
        } else if (tid < 252) {                // stage3: p=0..3, j=1..7
            int q = tid - 224;
            int p = q / 7, j = q - p * 7 + 1;
            float s3, c3;
            __sincosf((-(float)CUDART_PI / 16.0f) * (float)(p * j), &s3, &c3);
            sT[480 + q] = make_float2(c3, s3);
        }
    }

    // ---- Head: z = exp(i*(x+w0)); pair butterfly in-thread, vector store ----
#pragma unroll
    for (int j = 0; j < 2; j++) {
        int q = 2 * tid + j;
        float4 xv = xr[q];
        float4 wv = w4p[q];
        float s0, c0, s1, c1, s2, c2, s3, c3;
        __sincosf(xv.x + wv.x, &s0, &c0);
        __sincosf(xv.y + wv.y, &s1, &c1);
        __sincosf(xv.z + wv.z, &s2, &c2);
        __sincosf(xv.w + wv.w, &s3, &c3);
        float4* d4 = (float4*)(sA + F(4 * q));
        d4[0] = make_float4(c0 + c1, s0 + s1, c0 - c1, s0 - s1);
        d4[1] = make_float4(c2 + c3, s2 + s3, c2 - c3, s2 - s3);
    }
    __syncthreads();

    // ---- FFT 2048 = 8*8*8*4 Stockham: 3 radix-8 stages (packed) ----
    float2 w1save = stage8p<0>(sA, sB, tid, sT, C707P);
    __syncthreads();
    stage8p<3>(sB, sA, tid, sT + 256 + (tid >> 3) * 7, C707P);
    __syncthreads();
    stage8p<6>(sA, sB, tid, sT + 480 + (tid >> 6) * 7, C707P);
    __syncthreads();

    // ---- Final radix-4 in registers (packed); thread owns pairs
    //      n = 2t+512a (even, ue) and 2t+1+512a (odd, uo) ----
    ull ue[4], uo[4];
    {
        const ull* SB = (const ull*)sB;
        ulonglong2 L0 = *(const ulonglong2*)(SB + F(2 * tid + 0 * 512));
        ulonglong2 L1 = *(const ulonglong2*)(SB + F(2 * tid + 1 * 512));
        ulonglong2 L2 = *(const ulonglong2*)(SB + F(2 * tid + 2 * 512));
        ulonglong2 L3 = *(const ulonglong2*)(SB + F(2 * tid + 3 * 512));
        ull apc = padd(L0.x, L2.x), amc = psub(L0.x, L2.x);
        ull bpd = padd(L1.x, L3.x), bmd = psub(L1.x, L3.x);
        ull mb = pmi(bmd);
        ue[0] = padd(apc, bpd);
        ue[1] = padd(amc, mb);
        ue[2] = psub(apc, bpd);
        ue[3] = psub(amc, mb);
        ull epc = padd(L0.y, L2.y), emc = psub(L0.y, L2.y);
        ull fpd = padd(L1.y, L3.y), fmd = psub(L1.y, L3.y);
        ull mf = pmi(fmd);
        uo[0] = padd(epc, fpd);
        uo[1] = padd(emc, mf);
        uo[2] = psub(epc, fpd);
        uo[3] = psub(emc, mf);
    }

    // ---- Layer 1 twiddle (scalar cmul on unpacked halves) ----
    const float4* cw1_4 = (const float4*)g_cw1;
#pragma unroll
    for (int a = 0; a < 4; a++) {
        float4 cw = __ldg(&cw1_4[tid + 256 * a]);
        float xr_, xi_;
        up2(ue[a], xr_, xi_);
        ue[a] = pk2(xr_ * cw.x - xi_ * cw.y, xr_ * cw.y + xi_ * cw.x);
        up2(uo[a], xr_, xi_);
        uo[a] = pk2(xr_ * cw.z - xi_ * cw.w, xr_ * cw.w + xi_ * cw.z);
    }

    // ---- Tail DFT4s (packed): A_j over ue, B_j over uo ----
    float Ar[4], Ai[4], Br[4], Bi[4];
    {
        ull p0 = padd(ue[0], ue[2]), p1 = psub(ue[0], ue[2]);
        ull p2 = padd(ue[1], ue[3]), p3 = psub(ue[1], ue[3]);
        ull mp3 = pmi(p3);
        ull A0 = padd(p0, p2), A2 = psub(p0, p2);
        ull A1 = padd(p1, mp3), A3 = psub(p1, mp3);
        ull q0 = padd(uo[0], uo[2]), q1 = psub(uo[0], uo[2]);
        ull q2 = padd(uo[1], uo[3]), q3 = psub(uo[1], uo[3]);
        ull mq3 = pmi(q3);
        ull B0 = padd(q0, q2), B2 = psub(q0, q2);
        ull B1 = padd(q1, mq3), B3 = psub(q1, mq3);
        up2(A0, Ar[0], Ai[0]); up2(A1, Ar[1], Ai[1]);
        up2(A2, Ar[2], Ai[2]); up2(A3, Ar[3], Ai[3]);
        up2(B0, Br[0], Bi[0]); up2(B1, Br[1], Bi[1]);
        up2(B2, Br[2], Bi[2]); up2(B3, Br[3], Bi[3]);
    }

    // cos/sin(pi*k/1024), k=0..9 — compile-time constants
    const float CK[NCLS] = {1.0f, 0.99999529380957619f, 0.99998117528260111f,
                            0.99995764455196390f, 0.99992470183914450f,
                            0.99988234745421256f, 0.99983058179582340f,
                            0.99976940535121528f, 0.99969881869620425f,
                            0.99961882249517864f};
    const float SK[NCLS] = {0.0f, 0.0030679567629659761f, 0.0061358846491544753f,
                            0.0092037547820598194f, 0.012271538285719925f,
                            0.015339206284988100f, 0.018406729905804820f,
                            0.021474080275469508f, 0.024541228522912288f,
                            0.027608145778965740f};

    // v[20]: v[2k]=Re X_k, v[2k+1]=Im X_k (per-thread partial)
    float v[20];
    {
        // w1t = exp(-2*pi*i*t/1024) = (tw1[t])^2
        float2 w1t = make_float2(w1save.x * w1save.x - w1save.y * w1save.y,
                                 2.0f * w1save.x * w1save.y);
        float wkr = 1.0f, wki = 0.0f;
#pragma unroll
        for (int k = 0; k < NCLS; k++) {
            int j = k & 3;
            float alr = 1.0f + CK[k], ali = -SK[k];
            float ber = 1.0f - CK[k], bei = SK[k];
            float pr = alr * Ar[j] - ali * Ai[j] + ber * Br[j] - bei * Bi[j];
            float pi = alr * Ai[j] + ali * Ar[j] + ber * Bi[j] + bei * Br[j];
            v[2 * k]     = wkr * pr - wki * pi;
            v[2 * k + 1] = wkr * pi + wki * pr;
            float nwr = wkr * w1t.x - wki * w1t.y;
            wki = wkr * w1t.y + wki * w1t.x;
            wkr = nwr;
        }
    }

    // ---- Value-splitting warp reduction: 20 scalars -> 5 per lane ----
    const int lane = tid & 31;
    float h1[10];
    {
        const bool hi = (lane & 16);
#pragma unroll
        for (int j = 0; j < 10; j++) {
            float send = hi ? v[j] : v[j + 10];
            float recv = __shfl_xor_sync(0xFFFFFFFFu, send, 16);
            h1[j] = (hi ? v[j + 10] : v[j]) + recv;
        }
    }
    float h2[5];
    {
        const bool hi = (lane & 8);
#pragma unroll
        for (int j = 0; j < 5; j++) {
            float send = hi ? h1[j] : h1[j + 5];
            float recv = __shfl_xor_sync(0xFFFFFFFFu, send, 8);
            h2[j] = (hi ? h1[j + 5] : h1[j]) + recv;
        }
    }
#pragma unroll
    for (int off = 4; off > 0; off >>= 1) {
#pragma unroll
        for (int j = 0; j < 5; j++)
            h2[j] += __shfl_xor_sync(0xFFFFFFFFu, h2[j], off);
    }
    // lane L (L%8==0) holds scalars [5q..5q+4], q = (L>>3)&3

    // ---- Cross-warp reduction via sA ----
    float* red    = (float*)sA;                 // 8 warps * 20 scalars
    float* logits = (float*)sA + 8 * 20;
    const int wrp = tid >> 5;
    if ((lane & 7) == 0) {
        int base = wrp * 20 + ((lane >> 3) & 3) * 5;
#pragma unroll
        for (int j = 0; j < 5; j++) red[base + j] = h2[j];
    }
    __syncthreads();

    if (tid < NCLS) {
        float re = 0.f, im = 0.f;
#pragma unroll
        for (int wq = 0; wq < NT / 32; wq++) {
            re += red[wq * 20 + 2 * tid];
            im += red[wq * 20 + 2 * tid + 1];
        }
        float r2v = re * re + im * im;
        // sin(atan2(im,re)) = im/|z|; dropped norms are positive -> phases unchanged
        logits[tid] = (r2v > 0.f) ? 5.0f * im * rsqrtf(r2v) : 0.0f;
    }
    __syncthreads();

    if (tid < NCLS) {
        float m = -1e30f;
#pragma unroll
        for (int k = 0; k < NCLS; k++) m = fmaxf(m, logits[k]);
        float sum = 0.f;
#pragma unroll
        for (int k = 0; k < NCLS; k++) sum += __expf(logits[k] - m);
        out[(size_t)row * NCLS + tid] = __expf(logits[tid] - m) / sum;
    }
}

extern "C" void kernel_launch(void* const* d_in, const int* in_sizes, int n_in,
                              void* d_out, int out_size) {
    const float* x = (const float*)d_in[0];     // (8192, 2048) fp32
    const float* w = (const float*)d_in[1];     // (4096,) fp32
    float* out = (float*)d_out;                 // (8192, 10) fp32

    vpc_init<<<(N + 255) / 256, 256>>>(w);
    vpc_main<<<8192, NT>>>(x, w, out);
}

// round 8
// speedup vs baseline: 2.0571x; 1.0196x over previous
#include <cuda_runtime.h>
#include <math_constants.h>

#define N     2048
#define NT    256
#define NCLS  10
#define C707  0.70710678118654752440f

// pad mapping: 2 extra float2 per 16 -> conflict-free for stride 1/8/64/256
// patterns AND keeps 16-byte alignment of even-indexed elements.
#define F(i) ((i) + (((i) >> 4) << 1))
#define SPAD 2304

typedef unsigned long long ull;

__device__ float2 g_cw1[N];   // exp(i*w1[n]), row-invariant

__global__ void vpc_init(const float* __restrict__ w) {
    int i = blockIdx.x * blockDim.x + threadIdx.x;
    if (i < N) {
        float s, c;
        sincosf(w[N + i], &s, &c);
        g_cw1[i] = make_float2(c, s);
    }
}

// ---- packed f32x2 helpers (complex held as ull: lo=re, hi=im) ----
__device__ __forceinline__ ull pk2(float x, float y) {
    ull r; asm("mov.b64 %0,{%1,%2};" : "=l"(r) : "f"(x), "f"(y)); return r;
}
__device__ __forceinline__ void up2(ull z, float& x, float& y) {
    asm("mov.b64 {%0,%1},%2;" : "=f"(x), "=f"(y) : "l"(z));
}
__device__ __forceinline__ ull padd(ull a, ull b) {
    ull d; asm("add.rn.f32x2 %0,%1,%2;" : "=l"(d) : "l"(a), "l"(b)); return d;
}
__device__ __forceinline__ ull psub(ull a, ull b) {
    ull d; asm("sub.rn.f32x2 %0,%1,%2;" : "=l"(d) : "l"(a), "l"(b)); return d;
}
__device__ __forceinline__ ull pmul(ull a, ull b) {
    ull d; asm("mul.rn.f32x2 %0,%1,%2;" : "=l"(d) : "l"(a), "l"(b)); return d;
}
// z * (-i) = (im, -re)
__device__ __forceinline__ ull pmi(ull z) {
    float x, y; up2(z, x, y); return pk2(y, -x);
}

// Packed DFT8 (forward, W8 = e^{-i pi/4}); C707P = pk2(C707, C707)
#define DFT8P(x0,x1,x2,x3,x4,x5,x6,x7, X0,X1,X2,X3,X4,X5,X6,X7) do {           \
    ull t0 = padd(x0, x4), t1 = psub(x0, x4);                                  \
    ull t2 = padd(x2, x6), t3 = psub(x2, x6);                                  \
    ull E0 = padd(t0, t2), E2 = psub(t0, t2);                                  \
    ull m3 = pmi(t3);                                                          \
    ull E1 = padd(t1, m3), E3 = psub(t1, m3);                                  \
    ull s0 = padd(x1, x5), s1 = psub(x1, x5);                                  \
    ull s2 = padd(x3, x7), s3 = psub(x3, x7);                                  \
    ull O0 = padd(s0, s2), O2 = psub(s0, s2);                                  \
    ull n3 = pmi(s3);                                                          \
    ull O1 = padd(s1, n3), O3 = psub(s1, n3);                                  \
    ull W1O = pmul(C707P, padd(O1, pmi(O1)));                                  \
    ull W2O = pmi(O2);                                                         \
    ull W3O = pmul(C707P, psub(pmi(O3), O3));                                  \
    X0 = padd(E0, O0);  X4 = psub(E0, O0);                                     \
    X1 = padd(E1, W1O); X5 = psub(E1, W1O);                                    \
    X2 = padd(E2, W2O); X6 = psub(E2, W2O);                                    \
    X3 = padd(E3, W3O); X7 = psub(E3, W3O);                                    \
} while (0)

// One Stockham radix-8 stage, packed data path.
// w1 = first twiddle (broadcast LDS by caller); powers via chain (fma pipe).
template <int SL>
__device__ __forceinline__ void stage8p(const float2* __restrict__ src,
                                        float2* __restrict__ dst, int t,
                                        float2 w1, const ull C707P) {
    const int s = 1 << SL;
    const ull* S = (const ull*)src;
    ull a0 = S[F(t + 0 * 256)], a1 = S[F(t + 1 * 256)];
    ull a2 = S[F(t + 2 * 256)], a3 = S[F(t + 3 * 256)];
    ull a4 = S[F(t + 4 * 256)], a5 = S[F(t + 5 * 256)];
    ull a6 = S[F(t + 6 * 256)], a7 = S[F(t + 7 * 256)];
    ull X0, X1, X2, X3, X4, X5, X6, X7;
    DFT8P(a0, a1, a2, a3, a4, a5, a6, a7, X0, X1, X2, X3, X4, X5, X6, X7);

    const float wr1 = w1.x, wi1 = w1.y;
    const float wr2 = wr1 * wr1 - wi1 * wi1, wi2 = 2.0f * wr1 * wi1;
    const float wr3 = wr1 * wr2 - wi1 * wi2, wi3 = wr1 * wi2 + wi1 * wr2;
    const float wr4 = wr2 * wr2 - wi2 * wi2, wi4 = 2.0f * wr2 * wi2;
    const float wr5 = wr1 * wr4 - wi1 * wi4, wi5 = wr1 * wi4 + wi1 * wr4;
    const float wr6 = wr2 * wr4 - wi2 * wi4, wi6 = wr2 * wi4 + wi2 * wr4;
    const float wr7 = wr3 * wr4 - wi3 * wi4, wi7 = wr3 * wi4 + wi3 * wr4;

#define TW(XJ, WR, WI, xo, yo) do {                                            \
        float xr_, xi_; up2(XJ, xr_, xi_);                                     \
        xo = xr_ * (WR) - xi_ * (WI); yo = xr_ * (WI) + xi_ * (WR);            \
    } while (0)

    if (SL == 0) {
        // 8 contiguous outputs, pad-safe aligned run -> 4x STS.128
        float x1o, y1o, x2o, y2o, x3o, y3o, x4o, y4o, x5o, y5o, x6o, y6o, x7o, y7o;
        TW(X1, wr1, wi1, x1o, y1o); TW(X2, wr2, wi2, x2o, y2o);
        TW(X3, wr3, wi3, x3o, y3o); TW(X4, wr4, wi4, x4o, y4o);
        TW(X5, wr5, wi5, x5o, y5o); TW(X6, wr6, wi6, x6o, y6o);
        TW(X7, wr7, wi7, x7o, y7o);
        float x0o, y0o; up2(X0, x0o, y0o);
        float4* d4 = (float4*)(dst + F(8 * t));
        d4[0] = make_float4(x0o, y0o, x1o, y1o);
        d4[1] = make_float4(x2o, y2o, x3o, y3o);
        d4[2] = make_float4(x4o, y4o, x5o, y5o);
        d4[3] = make_float4(x6o, y6o, x7o, y7o);
    } else {
        int ob = (t & (s - 1)) + ((t >> SL) << (SL + 3));
        ((ull*)dst)[F(ob)] = X0;
#define APPL(XJ, J, WR, WI) do {                                               \
            float xr_, xi_; up2(XJ, xr_, xi_);                                 \
            dst[F(ob + (J) * s)] =                                             \
                make_float2(xr_ * (WR) - xi_ * (WI), xr_ * (WI) + xi_ * (WR)); \
        } while (0)
        APPL(X1, 1, wr1, wi1); APPL(X2, 2, wr2, wi2); APPL(X3, 3, wr3, wi3);
        APPL(X4, 4, wr4, wi4); APPL(X5, 5, wr5, wi5); APPL(X6, 6, wr6, wi6);
        APPL(X7, 7, wr7, wi7);
#undef APPL
    }
#undef TW
}

__global__ __launch_bounds__(NT, 5) void vpc_main(const float* __restrict__ x,
                                                  const float* __restrict__ w,
                                                  float* __restrict__ out) {
    __shared__ float2 sA[SPAD];
    __shared__ float2 sB[SPAD];
    __shared__ float2 sT[292];   // [0:256) tw1, [256:288) tw2, [288:292) tw3

    const int tid = threadIdx.x;
    const int row = blockIdx.x;
    const float4* xr  = (const float4*)(x + (size_t)row * N);
    const float4* w4p = (const float4*)w;
    const ull C707P = pk2(C707, C707);

    // ---- Twiddle table fill (once per CTA, overlapped with head) ----
    {
        float s, c;
        __sincosf((-(float)CUDART_PI / 1024.0f) * (float)tid, &s, &c);
        sT[tid] = make_float2(c, s);
        if (tid < 32) {                        // stage2 base: exp(-i*pi*p/128)
            float s2, c2;
            __sincosf((-(float)CUDART_PI / 128.0f) * (float)tid, &s2, &c2);
            sT[256 + tid] = make_float2(c2, s2);
        } else if (tid < 36) {                 // stage3 base: exp(-i*pi*p/16)
            int p = tid - 32;
            float s3, c3;
            __sincosf((-(float)CUDART_PI / 16.0f) * (float)p, &s3, &c3);
            sT[288 + p] = make_float2(c3, s3);
        }
    }

    // ---- Head: z = exp(i*(x+w0)); pair butterfly in-thread, vector store ----
#pragma unroll
    for (int j = 0; j < 2; j++) {
        int q = 2 * tid + j;
        float4 xv = xr[q];
        float4 wv = w4p[q];
        float s0, c0, s1, c1, s2, c2, s3, c3;
        __sincosf(xv.x + wv.x, &s0, &c0);
        __sincosf(xv.y + wv.y, &s1, &c1);
        __sincosf(xv.z + wv.z, &s2, &c2);
        __sincosf(xv.w + wv.w, &s3, &c3);
        float4* d4 = (float4*)(sA + F(4 * q));
        d4[0] = make_float4(c0 + c1, s0 + s1, c0 - c1, s0 - s1);
        d4[1] = make_float4(c2 + c3, s2 + s3, c2 - c3, s2 - s3);
    }
    __syncthreads();

    // ---- FFT 2048 = 8*8*8*4 Stockham: 3 radix-8 stages (packed) ----
    float2 w1save = sT[tid];
    stage8p<0>(sA, sB, tid, w1save, C707P);
    __syncthreads();
    stage8p<3>(sB, sA, tid, sT[256 + (tid >> 3)], C707P);
    __syncthreads();
    stage8p<6>(sA, sB, tid, sT[288 + (tid >> 6)], C707P);
    __syncthreads();

    // ---- Final radix-4 in registers (packed); thread owns pairs
    //      n = 2t+512a (even, ue) and 2t+1+512a (odd, uo) ----
    ull ue[4], uo[4];
    {
        const ull* SB = (const ull*)sB;
        ulonglong2 L0 = *(const ulonglong2*)(SB + F(2 * tid + 0 * 512));
        ulonglong2 L1 = *(const ulonglong2*)(SB + F(2 * tid + 1 * 512));
        ulonglong2 L2 = *(const ulonglong2*)(SB + F(2 * tid + 2 * 512));
        ulonglong2 L3 = *(const ulonglong2*)(SB + F(2 * tid + 3 * 512));
        ull apc = padd(L0.x, L2.x), amc = psub(L0.x, L2.x);
        ull bpd = padd(L1.x, L3.x), bmd = psub(L1.x, L3.x);
        ull mb = pmi(bmd);
        ue[0] = padd(apc, bpd);
        ue[1] = padd(amc, mb);
        ue[2] = psub(apc, bpd);
        ue[3] = psub(amc, mb);
        ull epc = padd(L0.y, L2.y), emc = psub(L0.y, L2.y);
        ull fpd = padd(L1.y, L3.y), fmd = psub(L1.y, L3.y);
        ull mf = pmi(fmd);
        uo[0] = padd(epc, fpd);
        uo[1] = padd(emc, mf);
        uo[2] = psub(epc, fpd);
        uo[3] = psub(emc, mf);
    }

    // ---- Layer 1 twiddle (scalar cmul on unpacked halves) ----
    const float4* cw1_4 = (const float4*)g_cw1;
#pragma unroll
    for (int a = 0; a < 4; a++) {
        float4 cw = __ldg(&cw1_4[tid + 256 * a]);
        float xr_, xi_;
        up2(ue[a], xr_, xi_);
        ue[a] = pk2(xr_ * cw.x - xi_ * cw.y, xr_ * cw.y + xi_ * cw.x);
        up2(uo[a], xr_, xi_);
        uo[a] = pk2(xr_ * cw.z - xi_ * cw.w, xr_ * cw.w + xi_ * cw.z);
    }

    // ---- Tail DFT4s (packed): A_j over ue, B_j over uo ----
    float Ar[4], Ai[4], Br[4], Bi[4];
    {
        ull p0 = padd(ue[0], ue[2]), p1 = psub(ue[0], ue[2]);
        ull p2 = padd(ue[1], ue[3]), p3 = psub(ue[1], ue[3]);
        ull mp3 = pmi(p3);
        ull A0 = padd(p0, p2), A2 = psub(p0, p2);
        ull A1 = padd(p1, mp3), A3 = psub(p1, mp3);
        ull q0 = padd(uo[0], uo[2]), q1 = psub(uo[0], uo[2]);
        ull q2 = padd(uo[1], uo[3]), q3 = psub(uo[1], uo[3]);
        ull mq3 = pmi(q3);
        ull B0 = padd(q0, q2), B2 = psub(q0, q2);
        ull B1 = padd(q1, mq3), B3 = psub(q1, mq3);
        up2(A0, Ar[0], Ai[0]); up2(A1, Ar[1], Ai[1]);
        up2(A2, Ar[2], Ai[2]); up2(A3, Ar[3], Ai[3]);
        up2(B0, Br[0], Bi[0]); up2(B1, Br[1], Bi[1]);
        up2(B2, Br[2], Bi[2]); up2(B3, Br[3], Bi[3]);
    }

    // cos/sin(pi*k/1024), k=0..9 — compile-time constants
    const float CK[NCLS] = {1.0f, 0.99999529380957619f, 0.99998117528260111f,
                            0.99995764455196390f, 0.99992470183914450f,
                            0.99988234745421256f, 0.99983058179582340f,
                            0.99976940535121528f, 0.99969881869620425f,
                            0.99961882249517864f};
    const float SK[NCLS] = {0.0f, 0.0030679567629659761f, 0.0061358846491544753f,
                            0.0092037547820598194f, 0.012271538285719925f,
                            0.015339206284988100f, 0.018406729905804820f,
                            0.021474080275469508f, 0.024541228522912288f,
                            0.027608145778965740f};

    // v[20]: v[2k]=Re X_k, v[2k+1]=Im X_k (per-thread partial)
    float v[20];
    {
        // w1t = exp(-2*pi*i*t/1024) = (tw1[t])^2
        float2 w1t = make_float2(w1save.x * w1save.x - w1save.y * w1save.y,
                                 2.0f * w1save.x * w1save.y);
        float wkr = 1.0f, wki = 0.0f;
#pragma unroll
        for (int k = 0; k < NCLS; k++) {
            int j = k & 3;
            float alr = 1.0f + CK[k], ali = -SK[k];
            float ber = 1.0f - CK[k], bei = SK[k];
            float pr = alr * Ar[j] - ali * Ai[j] + ber * Br[j] - bei * Bi[j];
            float pi = alr * Ai[j] + ali * Ar[j] + ber * Bi[j] + bei * Br[j];
            v[2 * k]     = wkr * pr - wki * pi;
            v[2 * k + 1] = wkr * pi + wki * pr;
            float nwr = wkr * w1t.x - wki * w1t.y;
            wki = wkr * w1t.y + wki * w1t.x;
            wkr = nwr;
        }
    }

    // ---- Value-splitting warp reduction: 20 scalars -> 5 per lane ----
    const int lane = tid & 31;
    float h1[10];
    {
        const bool hi = (lane & 16);
#pragma unroll
        for (int j = 0; j < 10; j++) {
            float send = hi ? v[j] : v[j + 10];
            float recv = __shfl_xor_sync(0xFFFFFFFFu, send, 16);
            h1[j] = (hi ? v[j + 10] : v[j]) + recv;
        }
    }
    float h2[5];
    {
        const bool hi = (lane & 8);
#pragma unroll
        for (int j = 0; j < 5; j++) {
            float send = hi ? h1[j] : h1[j + 5];
            float recv = __shfl_xor_sync(0xFFFFFFFFu, send, 8);
            h2[j] = (hi ? h1[j + 5] : h1[j]) + recv;
        }
    }
#pragma unroll
    for (int off = 4; off > 0; off >>= 1) {
#pragma unroll
        for (int j = 0; j < 5; j++)
            h2[j] += __shfl_xor_sync(0xFFFFFFFFu, h2[j], off);
    }
    // lane L (L%8==0) holds scalars [5q..5q+4], q = (L>>3)&3

    // ---- Cross-warp reduction via sA ----
    float* red    = (float*)sA;                 // 8 warps * 20 scalars
    float* logits = (float*)sA + 8 * 20;
    const int wrp = tid >> 5;
    if ((lane & 7) == 0) {
        int base = wrp * 20 + ((lane >> 3) & 3) * 5;
#pragma unroll
        for (int j = 0; j < 5; j++) red[base + j] = h2[j];
    }
    __syncthreads();

    if (tid < NCLS) {
        float re = 0.f, im = 0.f;
#pragma unroll
        for (int wq = 0; wq < NT / 32; wq++) {
            re += red[wq * 20 + 2 * tid];
            im += red[wq * 20 + 2 * tid + 1];
        }
        float r2v = re * re + im * im;
        // sin(atan2(im,re)) = im/|z|; dropped norms are positive -> phases unchanged
        logits[tid] = (r2v > 0.f) ? 5.0f * im * rsqrtf(r2v) : 0.0f;
    }
    __syncthreads();

    if (tid < NCLS) {
        float m = -1e30f;
#pragma unroll
        for (int k = 0; k < NCLS; k++) m = fmaxf(m, logits[k]);
        float sum = 0.f;
#pragma unroll
        for (int k = 0; k < NCLS; k++) sum += __expf(logits[k] - m);
        out[(size_t)row * NCLS + tid] = __expf(logits[tid] - m) / sum;
    }
}

extern "C" void kernel_launch(void* const* d_in, const int* in_sizes, int n_in,
                              void* d_out, int out_size) {
    const float* x = (const float*)d_in[0];     // (8192, 2048) fp32
    const float* w = (const float*)d_in[1];     // (4096,) fp32
    float* out = (float*)d_out;                 // (8192, 10) fp32

    vpc_init<<<(N + 255) / 256, 256>>>(w);
    vpc_main<<<8192, NT>>>(x, w, out);
}

// round 9
// speedup vs baseline: 2.1742x; 1.0569x over previous
#include <cuda_runtime.h>
#include <math_constants.h>

#define N     2048
#define NT    256
#define NCLS  10
#define C707  0.70710678118654752440f

// pad mapping: 2 extra float2 per 16 -> conflict-free for stride 1/8/64/256
// patterns AND keeps 16-byte alignment of even-indexed elements.
#define F(i) ((i) + (((i) >> 4) << 1))
#define SPAD 2304

typedef unsigned long long ull;

__device__ float2 g_cw1[N];   // exp(i*w1[n]), row-invariant

__global__ void vpc_init(const float* __restrict__ w) {
    int i = blockIdx.x * blockDim.x + threadIdx.x;
    if (i < N) {
        float s, c;
        sincosf(w[N + i], &s, &c);
        g_cw1[i] = make_float2(c, s);
    }
}

// ---- packed f32x2 helpers (complex held as ull: lo=re, hi=im) ----
__device__ __forceinline__ ull pk2(float x, float y) {
    ull r; asm("mov.b64 %0,{%1,%2};" : "=l"(r) : "f"(x), "f"(y)); return r;
}
__device__ __forceinline__ void up2(ull z, float& x, float& y) {
    asm("mov.b64 {%0,%1},%2;" : "=f"(x), "=f"(y) : "l"(z));
}
__device__ __forceinline__ ull padd(ull a, ull b) {
    ull d; asm("add.rn.f32x2 %0,%1,%2;" : "=l"(d) : "l"(a), "l"(b)); return d;
}
__device__ __forceinline__ ull psub(ull a, ull b) {
    ull d; asm("sub.rn.f32x2 %0,%1,%2;" : "=l"(d) : "l"(a), "l"(b)); return d;
}
__device__ __forceinline__ ull pmul(ull a, ull b) {
    ull d; asm("mul.rn.f32x2 %0,%1,%2;" : "=l"(d) : "l"(a), "l"(b)); return d;
}
// z * (-i) = (im, -re)
__device__ __forceinline__ ull pmi(ull z) {
    float x, y; up2(z, x, y); return pk2(y, -x);
}

// Packed DFT8 (forward, W8 = e^{-i pi/4}); C707P = pk2(C707, C707)
#define DFT8P(x0,x1,x2,x3,x4,x5,x6,x7, X0,X1,X2,X3,X4,X5,X6,X7) do {           \
    ull t0 = padd(x0, x4), t1 = psub(x0, x4);                                  \
    ull t2 = padd(x2, x6), t3 = psub(x2, x6);                                  \
    ull E0 = padd(t0, t2), E2 = psub(t0, t2);                                  \
    ull m3 = pmi(t3);                                                          \
    ull E1 = padd(t1, m3), E3 = psub(t1, m3);                                  \
    ull s0 = padd(x1, x5), s1 = psub(x1, x5);                                  \
    ull s2 = padd(x3, x7), s3 = psub(x3, x7);                                  \
    ull O0 = padd(s0, s2), O2 = psub(s0, s2);                                  \
    ull n3 = pmi(s3);                                                          \
    ull O1 = padd(s1, n3), O3 = psub(s1, n3);                                  \
    ull W1O = pmul(C707P, padd(O1, pmi(O1)));                                  \
    ull W2O = pmi(O2);                                                         \
    ull W3O = pmul(C707P, psub(pmi(O3), O3));                                  \
    X0 = padd(E0, O0);  X4 = psub(E0, O0);                                     \
    X1 = padd(E1, W1O); X5 = psub(E1, W1O);                                    \
    X2 = padd(E2, W2O); X6 = psub(E2, W2O);                                    \
    X3 = padd(E3, W3O); X7 = psub(E3, W3O);                                    \
} while (0)

// Twiddle power chain from w1 (fma pipe).
#define TWCHAIN(w1x, w1y)                                                      \
    const float wr1 = (w1x), wi1 = (w1y);                                      \
    const float wr2 = wr1 * wr1 - wi1 * wi1, wi2 = 2.0f * wr1 * wi1;           \
    const float wr3 = wr1 * wr2 - wi1 * wi2, wi3 = wr1 * wi2 + wi1 * wr2;      \
    const float wr4 = wr2 * wr2 - wi2 * wi2, wi4 = 2.0f * wr2 * wi2;           \
    const float wr5 = wr1 * wr4 - wi1 * wi4, wi5 = wr1 * wi4 + wi1 * wr4;      \
    const float wr6 = wr2 * wr4 - wi2 * wi4, wi6 = wr2 * wi4 + wi2 * wr4;      \
    const float wr7 = wr3 * wr4 - wi3 * wi4, wi7 = wr3 * wi4 + wi3 * wr4;

// Stages 2/3: gather stride-256 from shared, DFT8, twiddle, scatter.
template <int SL>
__device__ __forceinline__ void stage8p(const float2* __restrict__ src,
                                        float2* __restrict__ dst, int t,
                                        float2 w1, const ull C707P) {
    const int s = 1 << SL;
    const ull* S = (const ull*)src;
    ull a0 = S[F(t + 0 * 256)], a1 = S[F(t + 1 * 256)];
    ull a2 = S[F(t + 2 * 256)], a3 = S[F(t + 3 * 256)];
    ull a4 = S[F(t + 4 * 256)], a5 = S[F(t + 5 * 256)];
    ull a6 = S[F(t + 6 * 256)], a7 = S[F(t + 7 * 256)];
    ull X0, X1, X2, X3, X4, X5, X6, X7;
    DFT8P(a0, a1, a2, a3, a4, a5, a6, a7, X0, X1, X2, X3, X4, X5, X6, X7);

    TWCHAIN(w1.x, w1.y);
    int ob = (t & (s - 1)) + ((t >> SL) << (SL + 3));
    ((ull*)dst)[F(ob)] = X0;
#define APPL(XJ, J, WR, WI) do {                                               \
        float xr_, xi_; up2(XJ, xr_, xi_);                                     \
        dst[F(ob + (J) * s)] =                                                 \
            make_float2(xr_ * (WR) - xi_ * (WI), xr_ * (WI) + xi_ * (WR));     \
    } while (0)
    APPL(X1, 1, wr1, wi1); APPL(X2, 2, wr2, wi2); APPL(X3, 3, wr3, wi3);
    APPL(X4, 4, wr4, wi4); APPL(X5, 5, wr5, wi5); APPL(X6, 6, wr6, wi6);
    APPL(X7, 7, wr7, wi7);
#undef APPL
}

__global__ __launch_bounds__(NT, 5) void vpc_main(const float* __restrict__ x,
                                                  const float* __restrict__ w,
                                                  float* __restrict__ out) {
    __shared__ float2 sA[SPAD];
    __shared__ float2 sB[SPAD];
    __shared__ float2 sT[36];   // [0:32) stage2 base, [32:36) stage3 base

    const int tid = threadIdx.x;
    const int row = blockIdx.x;
    const float* xrow = x + (size_t)row * N;
    const ull C707P = pk2(C707, C707);

    // ---- Twiddle table fill (tiny; visible after first exchange sync) ----
    if (tid < 32) {                            // stage2 base: exp(-i*pi*p/128)
        float s2, c2;
        __sincosf((-(float)CUDART_PI / 128.0f) * (float)tid, &s2, &c2);
        sT[tid] = make_float2(c2, s2);
    } else if (tid < 36) {                     // stage3 base: exp(-i*pi*p/16)
        int p = tid - 32;
        float s3, c3;
        __sincosf((-(float)CUDART_PI / 16.0f) * (float)p, &s3, &c3);
        sT[32 + p] = make_float2(c3, s3);
    }

    // ---- Head fused into stage 1: gather post-butterfly z directly.
    //      z_bf[n] = e^{i(x+w)}[n&~1] +/- e^{i(x+w)}[(n&~1)+1], n = tid+256j ----
    const int tb = tid & ~1;
    const bool odd = (tid & 1);
    ull a[8];
#pragma unroll
    for (int j = 0; j < 8; j++) {
        int n = tb + 256 * j;
        float2 xv = *(const float2*)(xrow + n);
        float2 wv = __ldg((const float2*)(w + n));
        float s0, c0, s1, c1;
        __sincosf(xv.x + wv.x, &s0, &c0);
        __sincosf(xv.y + wv.y, &s1, &c1);
        a[j] = odd ? pk2(c0 - c1, s0 - s1) : pk2(c0 + c1, s0 + s1);
    }

    // w1 for stage 1 + tail (register sincos, no table)
    float2 w1save;
    __sincosf((-(float)CUDART_PI / 1024.0f) * (float)tid, &w1save.y, &w1save.x);

    // ---- Stage 1: DFT8 + twiddle, contiguous scatter (4x STS.128) ----
    {
        ull X0, X1, X2, X3, X4, X5, X6, X7;
        DFT8P(a[0], a[1], a[2], a[3], a[4], a[5], a[6], a[7],
              X0, X1, X2, X3, X4, X5, X6, X7);
        TWCHAIN(w1save.x, w1save.y);
        float x0o, y0o; up2(X0, x0o, y0o);
#define TW(XJ, WR, WI, xo, yo) do {                                            \
            float xr_, xi_; up2(XJ, xr_, xi_);                                 \
            xo = xr_ * (WR) - xi_ * (WI); yo = xr_ * (WI) + xi_ * (WR);        \
        } while (0)
        float x1o, y1o, x2o, y2o, x3o, y3o, x4o, y4o, x5o, y5o, x6o, y6o, x7o, y7o;
        TW(X1, wr1, wi1, x1o, y1o); TW(X2, wr2, wi2, x2o, y2o);
        TW(X3, wr3, wi3, x3o, y3o); TW(X4, wr4, wi4, x4o, y4o);
        TW(X5, wr5, wi5, x5o, y5o); TW(X6, wr6, wi6, x6o, y6o);
        TW(X7, wr7, wi7, x7o, y7o);
#undef TW
        float4* d4 = (float4*)(sA + F(8 * tid));
        d4[0] = make_float4(x0o, y0o, x1o, y1o);
        d4[1] = make_float4(x2o, y2o, x3o, y3o);
        d4[2] = make_float4(x4o, y4o, x5o, y5o);
        d4[3] = make_float4(x6o, y6o, x7o, y7o);
    }
    __syncthreads();

    // ---- Stages 2, 3 ----
    stage8p<3>(sA, sB, tid, sT[tid >> 3], C707P);
    __syncthreads();
    stage8p<6>(sB, sA, tid, sT[32 + (tid >> 6)], C707P);
    __syncthreads();

    // ---- Final radix-4 in registers (packed); thread owns pairs
    //      n = 2t+512a (even, ue) and 2t+1+512a (odd, uo) ----
    ull ue[4], uo[4];
    {
        const ull* SB = (const ull*)sA;
        ulonglong2 L0 = *(const ulonglong2*)(SB + F(2 * tid + 0 * 512));
        ulonglong2 L1 = *(const ulonglong2*)(SB + F(2 * tid + 1 * 512));
        ulonglong2 L2 = *(const ulonglong2*)(SB + F(2 * tid + 2 * 512));
        ulonglong2 L3 = *(const ulonglong2*)(SB + F(2 * tid + 3 * 512));
        ull apc = padd(L0.x, L2.x), amc = psub(L0.x, L2.x);
        ull bpd = padd(L1.x, L3.x), bmd = psub(L1.x, L3.x);
        ull mb = pmi(bmd);
        ue[0] = padd(apc, bpd);
        ue[1] = padd(amc, mb);
        ue[2] = psub(apc, bpd);
        ue[3] = psub(amc, mb);
        ull epc = padd(L0.y, L2.y), emc = psub(L0.y, L2.y);
        ull fpd = padd(L1.y, L3.y), fmd = psub(L1.y, L3.y);
        ull mf = pmi(fmd);
        uo[0] = padd(epc, fpd);
        uo[1] = padd(emc, mf);
        uo[2] = psub(epc, fpd);
        uo[3] = psub(emc, mf);
    }

    // ---- Layer 1 twiddle (scalar cmul on unpacked halves) ----
    const float4* cw1_4 = (const float4*)g_cw1;
#pragma unroll
    for (int a2 = 0; a2 < 4; a2++) {
        float4 cw = __ldg(&cw1_4[tid + 256 * a2]);
        float xr_, xi_;
        up2(ue[a2], xr_, xi_);
        ue[a2] = pk2(xr_ * cw.x - xi_ * cw.y, xr_ * cw.y + xi_ * cw.x);
        up2(uo[a2], xr_, xi_);
        uo[a2] = pk2(xr_ * cw.z - xi_ * cw.w, xr_ * cw.w + xi_ * cw.z);
    }

    // ---- Tail DFT4s (packed): A_j over ue, B_j over uo ----
    float Ar[4], Ai[4], Br[4], Bi[4];
    {
        ull p0 = padd(ue[0], ue[2]), p1 = psub(ue[0], ue[2]);
        ull p2 = padd(ue[1], ue[3]), p3 = psub(ue[1], ue[3]);
        ull mp3 = pmi(p3);
        ull A0 = padd(p0, p2), A2 = psub(p0, p2);
        ull A1 = padd(p1, mp3), A3 = psub(p1, mp3);
        ull q0 = padd(uo[0], uo[2]), q1 = psub(uo[0], uo[2]);
        ull q2 = padd(uo[1], uo[3]), q3 = psub(uo[1], uo[3]);
        ull mq3 = pmi(q3);
        ull B0 = padd(q0, q2), B2 = psub(q0, q2);
        ull B1 = padd(q1, mq3), B3 = psub(q1, mq3);
        up2(A0, Ar[0], Ai[0]); up2(A1, Ar[1], Ai[1]);
        up2(A2, Ar[2], Ai[2]); up2(A3, Ar[3], Ai[3]);
        up2(B0, Br[0], Bi[0]); up2(B1, Br[1], Bi[1]);
        up2(B2, Br[2], Bi[2]); up2(B3, Br[3], Bi[3]);
    }

    // cos/sin(pi*k/1024), k=0..9 — compile-time constants
    const float CK[NCLS] = {1.0f, 0.99999529380957619f, 0.99998117528260111f,
                            0.99995764455196390f, 0.99992470183914450f,
                            0.99988234745421256f, 0.99983058179582340f,
                            0.99976940535121528f, 0.99969881869620425f,
                            0.99961882249517864f};
    const float SK[NCLS] = {0.0f, 0.0030679567629659761f, 0.0061358846491544753f,
                            0.0092037547820598194f, 0.012271538285719925f,
                            0.015339206284988100f, 0.018406729905804820f,
                            0.021474080275469508f, 0.024541228522912288f,
                            0.027608145778965740f};

    // v[20]: v[2k]=Re X_k, v[2k+1]=Im X_k (per-thread partial)
    float v[20];
    {
        // w1t = exp(-2*pi*i*t/1024) = w1save^2
        float2 w1t = make_float2(w1save.x * w1save.x - w1save.y * w1save.y,
                                 2.0f * w1save.x * w1save.y);
        float wkr = 1.0f, wki = 0.0f;
#pragma unroll
        for (int k = 0; k < NCLS; k++) {
            int j = k & 3;
            float alr = 1.0f + CK[k], ali = -SK[k];
            float ber = 1.0f - CK[k], bei = SK[k];
            float pr = alr * Ar[j] - ali * Ai[j] + ber * Br[j] - bei * Bi[j];
            float pi = alr * Ai[j] + ali * Ar[j] + ber * Bi[j] + bei * Br[j];
            v[2 * k]     = wkr * pr - wki * pi;
            v[2 * k + 1] = wkr * pi + wki * pr;
            float nwr = wkr * w1t.x - wki * w1t.y;
            wki = wkr * w1t.y + wki * w1t.x;
            wkr = nwr;
        }
    }

    // ---- Value-splitting warp reduction: 20 scalars -> 5 per lane ----
    const int lane = tid & 31;
    float h1[10];
    {
        const bool hi = (lane & 16);
#pragma unroll
        for (int j = 0; j < 10; j++) {
            float send = hi ? v[j] : v[j + 10];
            float recv = __shfl_xor_sync(0xFFFFFFFFu, send, 16);
            h1[j] = (hi ? v[j + 10] : v[j]) + recv;
        }
    }
    float h2[5];
    {
        const bool hi = (lane & 8);
#pragma unroll
        for (int j = 0; j < 5; j++) {
            float send = hi ? h1[j] : h1[j + 5];
            float recv = __shfl_xor_sync(0xFFFFFFFFu, send, 8);
            h2[j] = (hi ? h1[j + 5] : h1[j]) + recv;
        }
    }
#pragma unroll
    for (int off = 4; off > 0; off >>= 1) {
#pragma unroll
        for (int j = 0; j < 5; j++)
            h2[j] += __shfl_xor_sync(0xFFFFFFFFu, h2[j], off);
    }
    // lane L (L%8==0) holds scalars [5q..5q+4], q = (L>>3)&3

    // ---- Cross-warp reduction via sB (sB's last reader was stage3, pre-sync) ----
    float* red    = (float*)sB;                 // 8 warps * 20 scalars
    float* logits = (float*)sB + 8 * 20;
    const int wrp = tid >> 5;
    if ((lane & 7) == 0) {
        int base = wrp * 20 + ((lane >> 3) & 3) * 5;
#pragma unroll
        for (int j = 0; j < 5; j++) red[base + j] = h2[j];
    }
    __syncthreads();

    if (tid < NCLS) {
        float re = 0.f, im = 0.f;
#pragma unroll
        for (int wq = 0; wq < NT / 32; wq++) {
            re += red[wq * 20 + 2 * tid];
            im += red[wq * 20 + 2 * tid + 1];
        }
        float r2v = re * re + im * im;
        // sin(atan2(im,re)) = im/|z|; dropped norms are positive -> phases unchanged
        logits[tid] = (r2v > 0.f) ? 5.0f * im * rsqrtf(r2v) : 0.0f;
    }
    __syncthreads();

    if (tid < NCLS) {
        float m = -1e30f;
#pragma unroll
        for (int k = 0; k < NCLS; k++) m = fmaxf(m, logits[k]);
        float sum = 0.f;
#pragma unroll
        for (int k = 0; k < NCLS; k++) sum += __expf(logits[k] - m);
        out[(size_t)row * NCLS + tid] = __expf(logits[tid] - m) / sum;
    }
}

extern "C" void kernel_launch(void* const* d_in, const int* in_sizes, int n_in,
                              void* d_out, int out_size) {
    const float* x = (const float*)d_in[0];     // (8192, 2048) fp32
    const float* w = (const float*)d_in[1];     // (4096,) fp32
    float* out = (float*)d_out;                 // (8192, 10) fp32

    vpc_init<<<(N + 255) / 256, 256>>>(w);
    vpc_main<<<8192, NT>>>(x, w, out);
}

// round 10
// speedup vs baseline: 2.1763x; 1.0010x over previous
#include <cuda_runtime.h>
#include <math_constants.h>

#define N     2048
#define NT    256
#define NCLS  10
#define C707  0.70710678118654752440f

// pad mapping: 2 extra float2 per 16 -> conflict-free for stride 1/8/64/256
// patterns AND keeps 16-byte alignment of even-indexed elements.
#define F(i) ((i) + (((i) >> 4) << 1))
#define SPAD 2304

typedef unsigned long long ull;

__device__ float2 g_cw1[N];   // exp(i*w1[n]), row-invariant

__global__ void vpc_init(const float* __restrict__ w) {
    int i = blockIdx.x * blockDim.x + threadIdx.x;
    if (i < N) {
        float s, c;
        sincosf(w[N + i], &s, &c);
        g_cw1[i] = make_float2(c, s);
    }
}

// ---- packed f32x2 helpers on float2 (union-bound; ptxas pairs registers,
//      no explicit MOVs, and .x/.y access is free) ----
union PU { ull u; float2 f; };

__device__ __forceinline__ float2 padd(float2 a, float2 b) {
    PU ua, ub, r; ua.f = a; ub.f = b;
    asm("add.rn.f32x2 %0,%1,%2;" : "=l"(r.u) : "l"(ua.u), "l"(ub.u));
    return r.f;
}
__device__ __forceinline__ float2 psub(float2 a, float2 b) {
    PU ua, ub, r; ua.f = a; ub.f = b;
    asm("sub.rn.f32x2 %0,%1,%2;" : "=l"(r.u) : "l"(ua.u), "l"(ub.u));
    return r.f;
}
__device__ __forceinline__ float2 pmul(float2 a, float2 b) {
    PU ua, ub, r; ua.f = a; ub.f = b;
    asm("mul.rn.f32x2 %0,%1,%2;" : "=l"(r.u) : "l"(ua.u), "l"(ub.u));
    return r.f;
}
__device__ __forceinline__ float2 pmi(float2 z) {      // z * (-i)
    return make_float2(z.y, -z.x);
}
__device__ __forceinline__ float2 cmul(float2 a, float2 b) {
    return make_float2(a.x * b.x - a.y * b.y, a.x * b.y + a.y * b.x);
}

// Packed DFT8 (forward, W8 = e^{-i pi/4})
#define DFT8P(x0,x1,x2,x3,x4,x5,x6,x7, X0,X1,X2,X3,X4,X5,X6,X7) do {           \
    float2 t0 = padd(x0, x4), t1 = psub(x0, x4);                               \
    float2 t2 = padd(x2, x6), t3 = psub(x2, x6);                               \
    float2 E0 = padd(t0, t2), E2 = psub(t0, t2);                               \
    float2 m3 = pmi(t3);                                                       \
    float2 E1 = padd(t1, m3), E3 = psub(t1, m3);                               \
    float2 s0 = padd(x1, x5), s1 = psub(x1, x5);                               \
    float2 s2 = padd(x3, x7), s3 = psub(x3, x7);                               \
    float2 O0 = padd(s0, s2), O2 = psub(s0, s2);                               \
    float2 n3 = pmi(s3);                                                       \
    float2 O1 = padd(s1, n3), O3 = psub(s1, n3);                               \
    float2 W1O = pmul(C707P, padd(O1, pmi(O1)));                               \
    float2 W2O = pmi(O2);                                                      \
    float2 W3O = pmul(C707P, psub(pmi(O3), O3));                               \
    X0 = padd(E0, O0);  X4 = psub(E0, O0);                                     \
    X1 = padd(E1, W1O); X5 = psub(E1, W1O);                                    \
    X2 = padd(E2, W2O); X6 = psub(E2, W2O);                                    \
    X3 = padd(E3, W3O); X7 = psub(E3, W3O);                                    \
} while (0)

// Stages 2/3: gather stride-256, DFT8, table twiddles (broadcast LDS), scatter.
template <int SL>
__device__ __forceinline__ void stage8t(const float2* __restrict__ src,
                                        float2* __restrict__ dst, int t,
                                        const float2* __restrict__ tw7,
                                        const float2 C707P) {
    const int s = 1 << SL;
    float2 a0 = src[F(t + 0 * 256)], a1 = src[F(t + 1 * 256)];
    float2 a2 = src[F(t + 2 * 256)], a3 = src[F(t + 3 * 256)];
    float2 a4 = src[F(t + 4 * 256)], a5 = src[F(t + 5 * 256)];
    float2 a6 = src[F(t + 6 * 256)], a7 = src[F(t + 7 * 256)];
    float2 X0, X1, X2, X3, X4, X5, X6, X7;
    DFT8P(a0, a1, a2, a3, a4, a5, a6, a7, X0, X1, X2, X3, X4, X5, X6, X7);

    int ob = (t & (s - 1)) + ((t >> SL) << (SL + 3));
    dst[F(ob)] = X0;
    dst[F(ob + 1 * s)] = cmul(X1, tw7[0]);
    dst[F(ob + 2 * s)] = cmul(X2, tw7[1]);
    dst[F(ob + 3 * s)] = cmul(X3, tw7[2]);
    dst[F(ob + 4 * s)] = cmul(X4, tw7[3]);
    dst[F(ob + 5 * s)] = cmul(X5, tw7[4]);
    dst[F(ob + 6 * s)] = cmul(X6, tw7[5]);
    dst[F(ob + 7 * s)] = cmul(X7, tw7[6]);
}

__global__ __launch_bounds__(NT, 5) void vpc_main(const float* __restrict__ x,
                                                  const float* __restrict__ w,
                                                  float* __restrict__ out) {
    __shared__ float2 sA[SPAD];
    __shared__ float2 sB[SPAD];
    __shared__ float2 sT[252];   // [0:224) stage2 (32 groups x 7), [224:252) stage3 (4 x 7)

    const int tid = threadIdx.x;
    const int row = blockIdx.x;
    const float* xrow = x + (size_t)row * N;
    const float2 C707P = make_float2(C707, C707);

    // ---- Twiddle tables (visible after first exchange sync) ----
    if (tid < 224) {                           // stage2: exp(-i*pi*p*j/128)
        int p = tid / 7, j = tid - 7 * p + 1;
        float s2, c2;
        __sincosf((-(float)CUDART_PI / 128.0f) * (float)(p * j), &s2, &c2);
        sT[tid] = make_float2(c2, s2);
    } else if (tid < 252) {                    // stage3: exp(-i*pi*p*j/16)
        int q = tid - 224;
        int p = q / 7, j = q - 7 * p + 1;
        float s3, c3;
        __sincosf((-(float)CUDART_PI / 16.0f) * (float)(p * j), &s3, &c3);
        sT[224 + q] = make_float2(c3, s3);
    }

    // ---- Head fused into stage 1: gather post-butterfly z directly.
    //      z_bf[n] = e^{i(x+w)}[n&~1] +/- e^{i(x+w)}[(n&~1)+1], n = tid+256j ----
    const int tb = tid & ~1;
    const bool odd = (tid & 1);
    float2 a[8];
#pragma unroll
    for (int j = 0; j < 8; j++) {
        int n = tb + 256 * j;
        float2 xv = *(const float2*)(xrow + n);
        float2 wv = __ldg((const float2*)(w + n));
        float s0, c0, s1, c1;
        __sincosf(xv.x + wv.x, &s0, &c0);
        __sincosf(xv.y + wv.y, &s1, &c1);
        a[j] = odd ? make_float2(c0 - c1, s0 - s1)
                   : make_float2(c0 + c1, s0 + s1);
    }

    // w1 for stage 1 + tail (register sincos)
    float2 w1save;
    __sincosf((-(float)CUDART_PI / 1024.0f) * (float)tid, &w1save.y, &w1save.x);

    // ---- Stage 1: DFT8 + chain twiddle, contiguous scatter (4x STS.128) ----
    {
        float2 X0, X1, X2, X3, X4, X5, X6, X7;
        DFT8P(a[0], a[1], a[2], a[3], a[4], a[5], a[6], a[7],
              X0, X1, X2, X3, X4, X5, X6, X7);
        float2 w1 = w1save;
        float2 w2 = cmul(w1, w1);
        float2 w3 = cmul(w1, w2);
        float2 w4 = cmul(w2, w2);
        float2 w5 = cmul(w1, w4);
        float2 w6 = cmul(w2, w4);
        float2 w7 = cmul(w3, w4);
        X1 = cmul(X1, w1); X2 = cmul(X2, w2); X3 = cmul(X3, w3);
        X4 = cmul(X4, w4); X5 = cmul(X5, w5); X6 = cmul(X6, w6);
        X7 = cmul(X7, w7);
        float4* d4 = (float4*)(sA + F(8 * tid));
        d4[0] = make_float4(X0.x, X0.y, X1.x, X1.y);
        d4[1] = make_float4(X2.x, X2.y, X3.x, X3.y);
        d4[2] = make_float4(X4.x, X4.y, X5.x, X5.y);
        d4[3] = make_float4(X6.x, X6.y, X7.x, X7.y);
    }
    __syncthreads();

    // ---- Stages 2, 3 (table twiddles) ----
    stage8t<3>(sA, sB, tid, sT + (tid >> 3) * 7, C707P);
    __syncthreads();
    stage8t<6>(sB, sA, tid, sT + 224 + (tid >> 6) * 7, C707P);
    __syncthreads();

    // ---- Final radix-4 in registers; thread owns pairs n=2t+512a, 2t+1+512a ----
    float2 ue[4], uo[4];
    {
        float4 p0 = *(const float4*)(sA + F(2 * tid + 0 * 512));
        float4 p1 = *(const float4*)(sA + F(2 * tid + 1 * 512));
        float4 p2 = *(const float4*)(sA + F(2 * tid + 2 * 512));
        float4 p3 = *(const float4*)(sA + F(2 * tid + 3 * 512));
        float2 b0 = make_float2(p0.x, p0.y), c0 = make_float2(p0.z, p0.w);
        float2 b1 = make_float2(p1.x, p1.y), c1 = make_float2(p1.z, p1.w);
        float2 b2 = make_float2(p2.x, p2.y), c2 = make_float2(p2.z, p2.w);
        float2 b3 = make_float2(p3.x, p3.y), c3 = make_float2(p3.z, p3.w);
        float2 apc = padd(b0, b2), amc = psub(b0, b2);
        float2 bpd = padd(b1, b3), bmd = psub(b1, b3);
        float2 mb = pmi(bmd);
        ue[0] = padd(apc, bpd);
        ue[1] = padd(amc, mb);
        ue[2] = psub(apc, bpd);
        ue[3] = psub(amc, mb);
        float2 epc = padd(c0, c2), emc = psub(c0, c2);
        float2 fpd = padd(c1, c3), fmd = psub(c1, c3);
        float2 mf = pmi(fmd);
        uo[0] = padd(epc, fpd);
        uo[1] = padd(emc, mf);
        uo[2] = psub(epc, fpd);
        uo[3] = psub(emc, mf);
    }

    // ---- Layer 1 twiddle ----
    const float4* cw1_4 = (const float4*)g_cw1;
#pragma unroll
    for (int a2 = 0; a2 < 4; a2++) {
        float4 cw = __ldg(&cw1_4[tid + 256 * a2]);
        ue[a2] = cmul(ue[a2], make_float2(cw.x, cw.y));
        uo[a2] = cmul(uo[a2], make_float2(cw.z, cw.w));
    }

    // ---- Tail DFT4s: A_j over ue, B_j over uo ----
    float2 A[4], B[4];
    {
        float2 p0 = padd(ue[0], ue[2]), p1 = psub(ue[0], ue[2]);
        float2 p2 = padd(ue[1], ue[3]), p3 = psub(ue[1], ue[3]);
        float2 mp3 = pmi(p3);
        A[0] = padd(p0, p2); A[2] = psub(p0, p2);
        A[1] = padd(p1, mp3); A[3] = psub(p1, mp3);
        float2 q0 = padd(uo[0], uo[2]), q1 = psub(uo[0], uo[2]);
        float2 q2 = padd(uo[1], uo[3]), q3 = psub(uo[1], uo[3]);
        float2 mq3 = pmi(q3);
        B[0] = padd(q0, q2); B[2] = psub(q0, q2);
        B[1] = padd(q1, mq3); B[3] = psub(q1, mq3);
    }

    // cos/sin(pi*k/1024), k=0..9 — compile-time constants
    const float CK[NCLS] = {1.0f, 0.99999529380957619f, 0.99998117528260111f,
                            0.99995764455196390f, 0.99992470183914450f,
                            0.99988234745421256f, 0.99983058179582340f,
                            0.99976940535121528f, 0.99969881869620425f,
                            0.99961882249517864f};
    const float SK[NCLS] = {0.0f, 0.0030679567629659761f, 0.0061358846491544753f,
                            0.0092037547820598194f, 0.012271538285719925f,
                            0.015339206284988100f, 0.018406729905804820f,
                            0.021474080275469508f, 0.024541228522912288f,
                            0.027608145778965740f};

    // v[20]: v[2k]=Re X_k, v[2k+1]=Im X_k (per-thread partial)
    float v[20];
    {
        // w1t = exp(-2*pi*i*t/1024) = w1save^2
        float2 w1t = cmul(w1save, w1save);
        float2 wk = make_float2(1.0f, 0.0f);
#pragma unroll
        for (int k = 0; k < NCLS; k++) {
            int j = k & 3;
            float alr = 1.0f + CK[k], ali = -SK[k];
            float ber = 1.0f - CK[k], bei = SK[k];
            float pr = alr * A[j].x - ali * A[j].y + ber * B[j].x - bei * B[j].y;
            float pi = alr * A[j].y + ali * A[j].x + ber * B[j].y + bei * B[j].x;
            v[2 * k]     = wk.x * pr - wk.y * pi;
            v[2 * k + 1] = wk.x * pi + wk.y * pr;
            wk = cmul(wk, w1t);
        }
    }

    // ---- Value-splitting warp reduction: 20 scalars -> 5 per lane ----
    const int lane = tid & 31;
    float h1[10];
    {
        const bool hi = (lane & 16);
#pragma unroll
        for (int j = 0; j < 10; j++) {
            float send = hi ? v[j] : v[j + 10];
            float recv = __shfl_xor_sync(0xFFFFFFFFu, send, 16);
            h1[j] = (hi ? v[j + 10] : v[j]) + recv;
        }
    }
    float h2[5];
    {
        const bool hi = (lane & 8);
#pragma unroll
        for (int j = 0; j < 5; j++) {
            float send = hi ? h1[j] : h1[j + 5];
            float recv = __shfl_xor_sync(0xFFFFFFFFu, send, 8);
            h2[j] = (hi ? h1[j + 5] : h1[j]) + recv;
        }
    }
#pragma unroll
    for (int off = 4; off > 0; off >>= 1) {
#pragma unroll
        for (int j = 0; j < 5; j++)
            h2[j] += __shfl_xor_sync(0xFFFFFFFFu, h2[j], off);
    }
    // lane L (L%8==0) holds scalars [5q..5q+4], q = (L>>3)&3

    // ---- Cross-warp reduction via sB ----
    float* red    = (float*)sB;                 // 8 warps * 20 scalars
    float* logits = (float*)sB + 8 * 20;
    const int wrp = tid >> 5;
    if ((lane & 7) == 0) {
        int base = wrp * 20 + ((lane >> 3) & 3) * 5;
#pragma unroll
        for (int j = 0; j < 5; j++) red[base + j] = h2[j];
    }
    __syncthreads();

    if (tid < NCLS) {
        float re = 0.f, im = 0.f;
#pragma unroll
        for (int wq = 0; wq < NT / 32; wq++) {
            re += red[wq * 20 + 2 * tid];
            im += red[wq * 20 + 2 * tid + 1];
        }
        float r2v = re * re + im * im;
        // sin(atan2(im,re)) = im/|z|; dropped norms are positive -> phases unchanged
        logits[tid] = (r2v > 0.f) ? 5.0f * im * rsqrtf(r2v) : 0.0f;
    }
    __syncthreads();

    if (tid < NCLS) {
        float m = -1e30f;
#pragma unroll
        for (int k = 0; k < NCLS; k++) m = fmaxf(m, logits[k]);
        float sum = 0.f;
#pragma unroll
        for (int k = 0; k < NCLS; k++) sum += __expf(logits[k] - m);
        out[(size_t)row * NCLS + tid] = __expf(logits[tid] - m) / sum;
    }
}

extern "C" void kernel_launch(void* const* d_in, const int* in_sizes, int n_in,
                              void* d_out, int out_size) {
    const float* x = (const float*)d_in[0];     // (8192, 2048) fp32
    const float* w = (const float*)d_in[1];     // (4096,) fp32
    float* out = (float*)d_out;                 // (8192, 10) fp32

    vpc_init<<<(N + 255) / 256, 256>>>(w);
    vpc_main<<<8192, NT>>>(x, w, out);
}

// round 12
// speedup vs baseline: 2.2650x; 1.0407x over previous
#include <cuda_runtime.h>
#include <math_constants.h>

#define N     2048
#define NT    256
#define NCLS  10
#define C707  0.70710678118654752440f

// pad mapping: 2 extra float2 per 16 -> conflict-free for stride 1/8/64/256
// patterns AND keeps 16-byte alignment of even-indexed elements.
#define F(i) ((i) + (((i) >> 4) << 1))
#define SPAD 2304

typedef unsigned long long ull;

__device__ float2 g_cw1[N];   // exp(i*w1[n]), row-invariant

__global__ void vpc_init(const float* __restrict__ w) {
    int i = blockIdx.x * blockDim.x + threadIdx.x;
    if (i < N) {
        float s, c;
        sincosf(w[N + i], &s, &c);
        g_cw1[i] = make_float2(c, s);
    }
}

union PU { ull u; float2 f; };
__device__ __forceinline__ float2 padd(float2 a, float2 b) {
    PU ua, ub, r; ua.f = a; ub.f = b;
    asm("add.rn.f32x2 %0,%1,%2;" : "=l"(r.u) : "l"(ua.u), "l"(ub.u));
    return r.f;
}
__device__ __forceinline__ float2 psub(float2 a, float2 b) {
    PU ua, ub, r; ua.f = a; ub.f = b;
    asm("sub.rn.f32x2 %0,%1,%2;" : "=l"(r.u) : "l"(ua.u), "l"(ub.u));
    return r.f;
}
__device__ __forceinline__ float2 pmul(float2 a, float2 b) {
    PU ua, ub, r; ua.f = a; ub.f = b;
    asm("mul.rn.f32x2 %0,%1,%2;" : "=l"(r.u) : "l"(ua.u), "l"(ub.u));
    return r.f;
}
__device__ __forceinline__ float2 pmi(float2 z) {      // z * (-i)
    return make_float2(z.y, -z.x);
}
__device__ __forceinline__ float2 cmul(float2 a, float2 b) {
    return make_float2(a.x * b.x - a.y * b.y, a.x * b.y + a.y * b.x);
}

// Second half of DFT8 given first-layer outputs t0..t3 (even), s0..s3 (odd).
#define DFT8_TAIL(t0,t1,t2,t3,s0,s1,s2,s3, X0,X1,X2,X3,X4,X5,X6,X7, C707P) do {\
    float2 E0 = padd(t0, t2), E2 = psub(t0, t2);                               \
    float2 m3 = pmi(t3);                                                       \
    float2 E1 = padd(t1, m3), E3 = psub(t1, m3);                               \
    float2 O0 = padd(s0, s2), O2 = psub(s0, s2);                               \
    float2 n3 = pmi(s3);                                                       \
    float2 O1 = padd(s1, n3), O3 = psub(s1, n3);                               \
    float2 W1O = pmul(C707P, padd(O1, pmi(O1)));                               \
    float2 W2O = pmi(O2);                                                      \
    float2 W3O = pmul(C707P, psub(pmi(O3), O3));                               \
    X0 = padd(E0, O0);  X4 = psub(E0, O0);                                     \
    X1 = padd(E1, W1O); X5 = psub(E1, W1O);                                    \
    X2 = padd(E2, W2O); X6 = psub(E2, W2O);                                    \
    X3 = padd(E3, W3O); X7 = psub(E3, W3O);                                    \
} while (0)

__global__ __launch_bounds__(NT, 6) void vpc_main(const float* __restrict__ x,
                                                  const float* __restrict__ w,
                                                  float* __restrict__ out) {
    __shared__ float2 sD[SPAD];
    __shared__ float2 sT[252];   // [0:224) stage2 (32x7), [224:252) stage3 (4x7)

    const int tid = threadIdx.x;
    const int row = blockIdx.x;
    const float* xrow = x + (size_t)row * N;
    const float2 C707P = make_float2(C707, C707);

    // ---- Twiddle tables (used first in stage 2, after >=1 barrier) ----
    if (tid < 224) {                           // stage2: exp(-i*pi*p*j/128)
        int p = tid / 7, j = tid - 7 * p + 1;
        float s2, c2;
        __sincosf((-(float)CUDART_PI / 128.0f) * (float)(p * j), &s2, &c2);
        sT[tid] = make_float2(c2, s2);
    } else if (tid < 252) {                    // stage3: exp(-i*pi*p*j/16)
        int q = tid - 224;
        int p = q / 7, j = q - 7 * p + 1;
        float s3, c3;
        __sincosf((-(float)CUDART_PI / 16.0f) * (float)(p * j), &s3, &c3);
        sT[224 + q] = make_float2(c3, s3);
    }

    // ---- Head fused into stage 1, interleaved with DFT8 first layer to
    //      minimize live registers. z_bf[n] = e^{i(x+w)}[nb] +/- e^{i(x+w)}[nb+1]
    const int tb = tid & ~1;
    const bool odd = (tid & 1);

#define HEADVAL(J, dst) do {                                                   \
        int n_ = tb + 256 * (J);                                               \
        float2 xv_ = *(const float2*)(xrow + n_);                              \
        float2 wv_ = __ldg((const float2*)(w + n_));                           \
        float s0_, c0_, s1_, c1_;                                              \
        __sincosf(xv_.x + wv_.x, &s0_, &c0_);                                  \
        __sincosf(xv_.y + wv_.y, &s1_, &c1_);                                  \
        dst = odd ? make_float2(c0_ - c1_, s0_ - s1_)                          \
                  : make_float2(c0_ + c1_, s0_ + s1_);                         \
    } while (0)

    float2 t0, t1, t2, t3, s0, s1, s2, s3;
    {
        float2 lo, hi;
        HEADVAL(0, lo); HEADVAL(4, hi); t0 = padd(lo, hi); t1 = psub(lo, hi);
        HEADVAL(1, lo); HEADVAL(5, hi); s0 = padd(lo, hi); s1 = psub(lo, hi);
        HEADVAL(2, lo); HEADVAL(6, hi); t2 = padd(lo, hi); t3 = psub(lo, hi);
        HEADVAL(3, lo); HEADVAL(7, hi); s2 = padd(lo, hi); s3 = psub(lo, hi);
    }
#undef HEADVAL

    // w1 for stage 1 + tail (register sincos)
    float2 w1save;
    __sincosf((-(float)CUDART_PI / 1024.0f) * (float)tid, &w1save.y, &w1save.x);

    // ---- Stage 1: finish DFT8, chain twiddle, contiguous store (4x STS.128) ----
    {
        float2 X0, X1, X2, X3, X4, X5, X6, X7;
        DFT8_TAIL(t0, t1, t2, t3, s0, s1, s2, s3,
                  X0, X1, X2, X3, X4, X5, X6, X7, C707P);
        float2 w1 = w1save;
        float2 w2 = cmul(w1, w1);
        float2 w3 = cmul(w1, w2);
        float2 w4 = cmul(w2, w2);
        X1 = cmul(X1, w1); X2 = cmul(X2, w2); X3 = cmul(X3, w3);
        X4 = cmul(X4, w4);
        X5 = cmul(X5, cmul(w1, w4));
        X6 = cmul(X6, cmul(w2, w4));
        X7 = cmul(X7, cmul(w3, w4));
        float4* d4 = (float4*)(sD + F(8 * tid));
        d4[0] = make_float4(X0.x, X0.y, X1.x, X1.y);
        d4[1] = make_float4(X2.x, X2.y, X3.x, X3.y);
        d4[2] = make_float4(X4.x, X4.y, X5.x, X5.y);
        d4[3] = make_float4(X6.x, X6.y, X7.x, X7.y);
    }
    __syncthreads();

    // ---- Stages 2 and 3: single-buffer (load -> barrier -> store) ----
#define STAGE(SL, TW7) do {                                                    \
        const int s_ = 1 << (SL);                                              \
        float2 x0_ = sD[F(tid + 0 * 256)], x4_ = sD[F(tid + 4 * 256)];         \
        float2 x2_ = sD[F(tid + 2 * 256)], x6_ = sD[F(tid + 6 * 256)];         \
        float2 x1_ = sD[F(tid + 1 * 256)], x5_ = sD[F(tid + 5 * 256)];         \
        float2 x3_ = sD[F(tid + 3 * 256)], x7_ = sD[F(tid + 7 * 256)];         \
        float2 u0 = padd(x0_, x4_), u1 = psub(x0_, x4_);                       \
        float2 u2 = padd(x2_, x6_), u3 = psub(x2_, x6_);                       \
        float2 v0 = padd(x1_, x5_), v1 = psub(x1_, x5_);                       \
        float2 v2 = padd(x3_, x7_), v3 = psub(x3_, x7_);                       \
        const float2* tw_ = (TW7);                                             \
        __syncthreads();                                                       \
        float2 X0, X1, X2, X3, X4, X5, X6, X7;                                 \
        DFT8_TAIL(u0, u1, u2, u3, v0, v1, v2, v3,                              \
                  X0, X1, X2, X3, X4, X5, X6, X7, C707P);                      \
        int ob_ = (tid & (s_ - 1)) + ((tid >> (SL)) << ((SL) + 3));            \
        sD[F(ob_)] = X0;                                                       \
        sD[F(ob_ + 1 * s_)] = cmul(X1, tw_[0]);                                \
        sD[F(ob_ + 2 * s_)] = cmul(X2, tw_[1]);                                \
        sD[F(ob_ + 3 * s_)] = cmul(X3, tw_[2]);                                \
        sD[F(ob_ + 4 * s_)] = cmul(X4, tw_[3]);                                \
        sD[F(ob_ + 5 * s_)] = cmul(X5, tw_[4]);                                \
        sD[F(ob_ + 6 * s_)] = cmul(X6, tw_[5]);                                \
        sD[F(ob_ + 7 * s_)] = cmul(X7, tw_[6]);                                \
        __syncthreads();                                                       \
    } while (0)

    STAGE(3, sT + (tid >> 3) * 7);
    STAGE(6, sT + 224 + (tid >> 6) * 7);
#undef STAGE

    // ---- Final radix-4 in registers; thread owns pairs n=2t+512a, 2t+1+512a ----
    float2 ue[4], uo[4];
    {
        float4 p0 = *(const float4*)(sD + F(2 * tid + 0 * 512));
        float4 p1 = *(const float4*)(sD + F(2 * tid + 1 * 512));
        float4 p2 = *(const float4*)(sD + F(2 * tid + 2 * 512));
        float4 p3 = *(const float4*)(sD + F(2 * tid + 3 * 512));
        float2 b0 = make_float2(p0.x, p0.y), c0 = make_float2(p0.z, p0.w);
        float2 b1 = make_float2(p1.x, p1.y), c1 = make_float2(p1.z, p1.w);
        float2 b2 = make_float2(p2.x, p2.y), c2 = make_float2(p2.z, p2.w);
        float2 b3 = make_float2(p3.x, p3.y), c3 = make_float2(p3.z, p3.w);
        float2 apc = padd(b0, b2), amc = psub(b0, b2);
        float2 bpd = padd(b1, b3), bmd = psub(b1, b3);
        float2 mb = pmi(bmd);
        ue[0] = padd(apc, bpd);
        ue[1] = padd(amc, mb);
        ue[2] = psub(apc, bpd);
        ue[3] = psub(amc, mb);
        float2 epc = padd(c0, c2), emc = psub(c0, c2);
        float2 fpd = padd(c1, c3), fmd = psub(c1, c3);
        float2 mf = pmi(fmd);
        uo[0] = padd(epc, fpd);
        uo[1] = padd(emc, mf);
        uo[2] = psub(epc, fpd);
        uo[3] = psub(emc, mf);
    }

    // ---- Layer 1 twiddle ----
    const float4* cw1_4 = (const float4*)g_cw1;
#pragma unroll
    for (int a2 = 0; a2 < 4; a2++) {
        float4 cw = __ldg(&cw1_4[tid + 256 * a2]);
        ue[a2] = cmul(ue[a2], make_float2(cw.x, cw.y));
        uo[a2] = cmul(uo[a2], make_float2(cw.z, cw.w));
    }

    // ---- Tail DFT4s, then P/M form ----
    float2 P[4], M[4];
    {
        float2 p0 = padd(ue[0], ue[2]), p1 = psub(ue[0], ue[2]);
        float2 p2 = padd(ue[1], ue[3]), p3 = psub(ue[1], ue[3]);
        float2 mp3 = pmi(p3);
        float2 A0 = padd(p0, p2), A2 = psub(p0, p2);
        float2 A1 = padd(p1, mp3), A3 = psub(p1, mp3);
        float2 q0 = padd(uo[0], uo[2]), q1 = psub(uo[0], uo[2]);
        float2 q2 = padd(uo[1], uo[3]), q3 = psub(uo[1], uo[3]);
        float2 mq3 = pmi(q3);
        float2 B0 = padd(q0, q2), B2 = psub(q0, q2);
        float2 B1 = padd(q1, mq3), B3 = psub(q1, mq3);
        P[0] = padd(A0, B0); M[0] = psub(A0, B0);
        P[1] = padd(A1, B1); M[1] = psub(A1, B1);
        P[2] = padd(A2, B2); M[2] = psub(A2, B2);
        P[3] = padd(A3, B3); M[3] = psub(A3, B3);
    }

    // cos/sin(pi*k/1024), k=0..9 — compile-time constants
    const float CK[NCLS] = {1.0f, 0.99999529380957619f, 0.99998117528260111f,
                            0.99995764455196390f, 0.99992470183914450f,
                            0.99988234745421256f, 0.99983058179582340f,
                            0.99976940535121528f, 0.99969881869620425f,
                            0.99961882249517864f};
    const float SK[NCLS] = {0.0f, 0.0030679567629659761f, 0.0061358846491544753f,
                            0.0092037547820598194f, 0.012271538285719925f,
                            0.015339206284988100f, 0.018406729905804820f,
                            0.021474080275469508f, 0.024541228522912288f,
                            0.027608145778965740f};

    // v[20]: X_k partial = cmul(wk, P_j + cmul((CK,-SK), M_j)), j = k&3
    float v[20];
    {
        float2 w1t = cmul(w1save, w1save);   // exp(-2*pi*i*t/1024)
        float2 wk = make_float2(1.0f, 0.0f);
#pragma unroll
        for (int k = 0; k < NCLS; k++) {
            int j = k & 3;
            float2 cM = make_float2(CK[k] * M[j].x + SK[k] * M[j].y,
                                    CK[k] * M[j].y - SK[k] * M[j].x);
            float2 inner = padd(P[j], cM);
            float2 ac = cmul(wk, inner);
            v[2 * k] = ac.x; v[2 * k + 1] = ac.y;
            wk = cmul(wk, w1t);
        }
    }

    // ---- Value-splitting warp reduction: 20 scalars -> 5 per lane ----
    const int lane = tid & 31;
    float h1[10];
    {
        const bool hi = (lane & 16);
#pragma unroll
        for (int j = 0; j < 10; j++) {
            float send = hi ? v[j] : v[j + 10];
            float recv = __shfl_xor_sync(0xFFFFFFFFu, send, 16);
            h1[j] = (hi ? v[j + 10] : v[j]) + recv;
        }
    }
    float h2[5];
    {
        const bool hi = (lane & 8);
#pragma unroll
        for (int j = 0; j < 5; j++) {
            float send = hi ? h1[j] : h1[j + 5];
            float recv = __shfl_xor_sync(0xFFFFFFFFu, send, 8);
            h2[j] = (hi ? h1[j + 5] : h1[j]) + recv;
        }
    }
#pragma unroll
    for (int off = 4; off > 0; off >>= 1) {
#pragma unroll
        for (int j = 0; j < 5; j++)
            h2[j] += __shfl_xor_sync(0xFFFFFFFFu, h2[j], off);
    }
    // lane L (L%8==0) holds scalars [5q..5q+4], q = (L>>3)&3

    // ---- Cross-warp reduction reusing sD (barrier: all final reads done) ----
    __syncthreads();
    float* red    = (float*)sD;                 // 8 warps * 20 scalars
    float* logits = (float*)sD + 8 * 20;
    const int wrp = tid >> 5;
    if ((lane & 7) == 0) {
        int base = wrp * 20 + ((lane >> 3) & 3) * 5;
#pragma unroll
        for (int j = 0; j < 5; j++) red[base + j] = h2[j];
    }
    __syncthreads();

    if (tid < NCLS) {
        float re = 0.f, im = 0.f;
#pragma unroll
        for (int wq = 0; wq < NT / 32; wq++) {
            re += red[wq * 20 + 2 * tid];
            im += red[wq * 20 + 2 * tid + 1];
        }
        float r2v = re * re + im * im;
        // sin(atan2(im,re)) = im/|z|; dropped norms are positive -> phases unchanged
        logits[tid] = (r2v > 0.f) ? 5.0f * im * rsqrtf(r2v) : 0.0f;
    }
    __syncthreads();

    if (tid < NCLS) {
        float m = -1e30f;
#pragma unroll
        for (int k = 0; k < NCLS; k++) m = fmaxf(m, logits[k]);
        float sum = 0.f;
#pragma unroll
        for (int k = 0; k < NCLS; k++) sum += __expf(logits[k] - m);
        out[(size_t)row * NCLS + tid] = __expf(logits[tid] - m) / sum;
    }
}

extern "C" void kernel_launch(void* const* d_in, const int* in_sizes, int n_in,
                              void* d_out, int out_size) {
    const float* x = (const float*)d_in[0];     // (8192, 2048) fp32
    const float* w = (const float*)d_in[1];     // (4096,) fp32
    float* out = (float*)d_out;                 // (8192, 10) fp32

    vpc_init<<<(N + 255) / 256, 256>>>(w);
    vpc_main<<<8192, NT>>>(x, w, out);
}

// round 13
// speedup vs baseline: 2.7470x; 1.2128x over previous
#include <cuda_runtime.h>
#include <math_constants.h>

#define N     2048
#define NT    128
#define NCLS  10
#define C707  0.70710678118654752440f

typedef unsigned long long ull;

__device__ float2 g_cw1[N];   // exp(i*w1[n]), row-invariant

__global__ void vpc_init(const float* __restrict__ w) {
    int i = blockIdx.x * blockDim.x + threadIdx.x;
    if (i < N) {
        float s, c;
        sincosf(w[N + i], &s, &c);
        g_cw1[i] = make_float2(c, s);
    }
}

union PU { ull u; float2 f; };
__device__ __forceinline__ float2 padd(float2 a, float2 b) {
    PU ua, ub, r; ua.f = a; ub.f = b;
    asm("add.rn.f32x2 %0,%1,%2;" : "=l"(r.u) : "l"(ua.u), "l"(ub.u));
    return r.f;
}
__device__ __forceinline__ float2 psub(float2 a, float2 b) {
    PU ua, ub, r; ua.f = a; ub.f = b;
    asm("sub.rn.f32x2 %0,%1,%2;" : "=l"(r.u) : "l"(ua.u), "l"(ub.u));
    return r.f;
}
__device__ __forceinline__ float2 pmul(float2 a, float2 b) {
    PU ua, ub, r; ua.f = a; ub.f = b;
    asm("mul.rn.f32x2 %0,%1,%2;" : "=l"(r.u) : "l"(ua.u), "l"(ub.u));
    return r.f;
}
__device__ __forceinline__ float2 pmi(float2 z) {      // z * (-i)
    return make_float2(z.y, -z.x);
}
__device__ __forceinline__ float2 cmul(float2 a, float2 b) {
    return make_float2(a.x * b.x - a.y * b.y, a.x * b.y + a.y * b.x);
}

// DFT4 (forward, W4 = -i)
#define DFT4P(x0,x1,x2,x3, X0,X1,X2,X3) do {                                   \
    float2 t_ = padd(x0, x2), u_ = psub(x0, x2);                               \
    float2 v_ = padd(x1, x3), s_ = psub(x1, x3);                               \
    float2 ms_ = pmi(s_);                                                      \
    X0 = padd(t_, v_); X1 = padd(u_, ms_);                                     \
    X2 = psub(t_, v_); X3 = psub(u_, ms_);                                     \
} while (0)

// DFT8 second half given first-layer outputs (as in prior rounds)
#define DFT8_TAIL(t0,t1,t2,t3,s0,s1,s2,s3, X0,X1,X2,X3,X4,X5,X6,X7, C707P) do {\
    float2 E0 = padd(t0, t2), E2 = psub(t0, t2);                               \
    float2 m3 = pmi(t3);                                                       \
    float2 E1 = padd(t1, m3), E3 = psub(t1, m3);                               \
    float2 O0 = padd(s0, s2), O2 = psub(s0, s2);                               \
    float2 n3 = pmi(s3);                                                       \
    float2 O1 = padd(s1, n3), O3 = psub(s1, n3);                               \
    float2 W1O = pmul(C707P, padd(O1, pmi(O1)));                               \
    float2 W2O = pmi(O2);                                                      \
    float2 W3O = pmul(C707P, psub(pmi(O3), O3));                               \
    X0 = padd(E0, O0);  X4 = psub(E0, O0);                                     \
    X1 = padd(E1, W1O); X5 = psub(E1, W1O);                                    \
    X2 = padd(E2, W2O); X6 = psub(E2, W2O);                                    \
    X3 = padd(E3, W3O); X7 = psub(E3, W3O);                                    \
} while (0)

__device__ __forceinline__ void dft8(const float2* x, float2* X, float2 C707P) {
    float2 u0 = padd(x[0], x[4]), u1 = psub(x[0], x[4]);
    float2 u2 = padd(x[2], x[6]), u3 = psub(x[2], x[6]);
    float2 v0 = padd(x[1], x[5]), v1 = psub(x[1], x[5]);
    float2 v2 = padd(x[3], x[7]), v3 = psub(x[3], x[7]);
    DFT8_TAIL(u0, u1, u2, u3, v0, v1, v2, v3,
              X[0], X[1], X[2], X[3], X[4], X[5], X[6], X[7], C707P);
}

// DFT16: G[k1] = sum_p g[p] W16^{p k1}, p = b + 4a, k1 = c + 4d.
__device__ __forceinline__ void dft16(float2* g, float2* O) {
    // stage 1: per b, DFT4 over a on {g[b], g[b+4], g[b+8], g[b+12]},
    // result T_b[c] stored to g[4c+b] (same slot set).
#pragma unroll
    for (int b = 0; b < 4; b++) {
        float2 X0, X1, X2, X3;
        DFT4P(g[b], g[b + 4], g[b + 8], g[b + 12], X0, X1, X2, X3);
        g[b] = X0; g[b + 4] = X1; g[b + 8] = X2; g[b + 12] = X3;
    }
    // twiddle W16^{b c} on g[4c+b]
    const float2 W1 = make_float2(0.92387953251128674f, -0.38268343236508978f);
    const float2 W2 = make_float2(C707, -C707);
    const float2 W3 = make_float2(0.38268343236508978f, -0.92387953251128674f);
    const float2 W6 = make_float2(-C707, -C707);
    const float2 W9 = make_float2(-0.92387953251128674f, 0.38268343236508978f);
    g[5]  = cmul(g[5],  W1); g[6]  = cmul(g[6],  W2); g[7]  = cmul(g[7],  W3);
    g[9]  = cmul(g[9],  W2); g[10] = pmi(g[10]);      g[11] = cmul(g[11], W6);
    g[13] = cmul(g[13], W3); g[14] = cmul(g[14], W6); g[15] = cmul(g[15], W9);
    // stage 2: per c, DFT4 over b on g[4c+0..3] -> O[c+4d]
#pragma unroll
    for (int c = 0; c < 4; c++) {
        float2 X0, X1, X2, X3;
        DFT4P(g[4 * c], g[4 * c + 1], g[4 * c + 2], g[4 * c + 3], X0, X1, X2, X3);
        O[c] = X0; O[c + 4] = X1; O[c + 8] = X2; O[c + 12] = X3;
    }
}

// O[k] *= w1^k, k=1..15 (shallow power tree)
__device__ __forceinline__ void twiddle15(float2* O, float2 w1) {
    float2 w2 = cmul(w1, w1), w3 = cmul(w1, w2), w4 = cmul(w2, w2);
    float2 w5 = cmul(w1, w4), w6 = cmul(w2, w4), w7 = cmul(w3, w4);
    float2 w8 = cmul(w4, w4);
    O[1] = cmul(O[1], w1);  O[2] = cmul(O[2], w2);  O[3] = cmul(O[3], w3);
    O[4] = cmul(O[4], w4);  O[5] = cmul(O[5], w5);  O[6] = cmul(O[6], w6);
    O[7] = cmul(O[7], w7);  O[8] = cmul(O[8], w8);
    O[9]  = cmul(O[9],  cmul(w1, w8)); O[10] = cmul(O[10], cmul(w2, w8));
    O[11] = cmul(O[11], cmul(w3, w8)); O[12] = cmul(O[12], cmul(w4, w8));
    O[13] = cmul(O[13], cmul(w5, w8)); O[14] = cmul(O[14], cmul(w6, w8));
    O[15] = cmul(O[15], cmul(w7, w8));
}

// n = 128 p + q decomposition; k = k1 + 16 k2; k2 = alpha + 16 beta.
// Z[k1+16a+256b] = sum_v W8^{vb} [ W128^{va} sum_u W16^{ua} (W2048^{qk1} G_q(k1)) ]
__global__ __launch_bounds__(NT, 10) void vpc_main(const float* __restrict__ x,
                                                   const float* __restrict__ w,
                                                   float* __restrict__ out) {
    __shared__ __align__(16) float2 sA[2304];

    const int q = threadIdx.x;      // 0..127
    const int row = blockIdx.x;
    const float* xrow = x + (size_t)row * N;
    const float2 C707P = make_float2(C707, C707);

    // ---- Phase 1: head (z = exp(i(x+w0)), pair butterfly) + local DFT16 over p
    const int qb = q & ~1;
    const bool odd = (q & 1);
    float2 g[16], O[16];
#pragma unroll
    for (int p = 0; p < 16; p++) {
        int nb = 128 * p + qb;
        float2 xv = *(const float2*)(xrow + nb);
        float2 wv = __ldg((const float2*)(w + nb));
        float s0, c0, s1, c1;
        __sincosf(xv.x + wv.x, &s0, &c0);
        __sincosf(xv.y + wv.y, &s1, &c1);
        g[p] = odd ? make_float2(c0 - c1, s0 - s1)
                   : make_float2(c0 + c1, s0 + s1);
    }
    dft16(g, O);
    float2 wq;
    __sincosf((-(float)CUDART_PI / 1024.0f) * (float)q, &wq.y, &wq.x);  // W2048^q
    twiddle15(O, wq);
    // layout A: addr = 17*q + k1 (conflict-free stores/gathers)
#pragma unroll
    for (int k = 0; k < 16; k++) sA[17 * q + k] = O[k];
    __syncthreads();

    // ---- Phase 2a: DFT16 over u (q = 8u+v) for fixed (k1, v) ----
    const int k1 = q & 15, vg = q >> 4;
#pragma unroll
    for (int u = 0; u < 16; u++) g[u] = sA[17 * (8 * u + vg) + k1];
    __syncthreads();
    dft16(g, O);
    float2 wv2;
    __sincosf((-(float)CUDART_PI / 64.0f) * (float)vg, &wv2.y, &wv2.x); // W128^v
    twiddle15(O, wv2);
    // layout B: addr = 288*v + 18*alpha + k1
#pragma unroll
    for (int al = 0; al < 16; al++) sA[288 * vg + 18 * al + k1] = O[al];
    __syncthreads();

    // ---- Phase 2b: DFT8 over v + layer1 + tail, all in registers ----
    // thread q ends with Z at n = 2q+256*beta (even) and 2q+1+256*beta (odd):
    // k1e + 16*alpha == 2q with alpha = q>>3, k1e = 2*(q&7).
    const int al2 = q >> 3;
    const int k1e = 2 * (q & 7);
    float2 Zi[8], Qi[8];
#pragma unroll
    for (int v2 = 0; v2 < 8; v2++) {
        float4 P4 = *(const float4*)(sA + 288 * v2 + 18 * al2 + k1e);
        Zi[v2] = make_float2(P4.x, P4.y);
        Qi[v2] = make_float2(P4.z, P4.w);
    }
    float2 A[8], B[8];
    dft8(Zi, A, C707P);   // A[beta] = Z[2q + 256 beta]
    dft8(Qi, B, C707P);   // B[beta] = Z[2q+1 + 256 beta]

    // layer 1 (×exp(i w1)) + pair butterfly -> pb (sum), mb (diff)
#pragma unroll
    for (int b2 = 0; b2 < 8; b2++) {
        float4 cw = __ldg(&((const float4*)g_cw1)[q + 128 * b2]);
        float2 ue = cmul(A[b2], make_float2(cw.x, cw.y));
        float2 uo = cmul(B[b2], make_float2(cw.z, cw.w));
        A[b2] = padd(ue, uo);
        B[b2] = psub(ue, uo);
    }
    float2 Pj[8], Mj[8];
    dft8(A, Pj, C707P);
    dft8(B, Mj, C707P);

    // cos/sin(pi*k/1024), k=0..9
    const float CK[NCLS] = {1.0f, 0.99999529380957619f, 0.99998117528260111f,
                            0.99995764455196390f, 0.99992470183914450f,
                            0.99988234745421256f, 0.99983058179582340f,
                            0.99976940535121528f, 0.99969881869620425f,
                            0.99961882249517864f};
    const float SK[NCLS] = {0.0f, 0.0030679567629659761f, 0.0061358846491544753f,
                            0.0092037547820598194f, 0.012271538285719925f,
                            0.015339206284988100f, 0.018406729905804820f,
                            0.021474080275469508f, 0.024541228522912288f,
                            0.027608145778965740f};

    // X_k partial = wt^k (P[j] + (CK,-SK)·M[j]),  j=k&7,  wt = W1024^q
    float rv[20];
    {
        float2 wt;
        __sincosf((-(float)CUDART_PI / 512.0f) * (float)q, &wt.y, &wt.x);
        float2 wk = make_float2(1.0f, 0.0f);
#pragma unroll
        for (int k = 0; k < NCLS; k++) {
            int j = k & 7;
            float2 cM = make_float2(CK[k] * Mj[j].x + SK[k] * Mj[j].y,
                                    CK[k] * Mj[j].y - SK[k] * Mj[j].x);
            float2 inner = padd(Pj[j], cM);
            float2 ac = cmul(wk, inner);
            rv[2 * k] = ac.x; rv[2 * k + 1] = ac.y;
            wk = cmul(wk, wt);
        }
    }

    // ---- Value-splitting warp reduction: 20 scalars -> 5 per lane ----
    const int lane = q & 31;
    float h1[10];
    {
        const bool hi = (lane & 16);
#pragma unroll
        for (int j = 0; j < 10; j++) {
            float send = hi ? rv[j] : rv[j + 10];
            float recv = __shfl_xor_sync(0xFFFFFFFFu, send, 16);
            h1[j] = (hi ? rv[j + 10] : rv[j]) + recv;
        }
    }
    float h2[5];
    {
        const bool hi = (lane & 8);
#pragma unroll
        for (int j = 0; j < 5; j++) {
            float send = hi ? h1[j] : h1[j + 5];
            float recv = __shfl_xor_sync(0xFFFFFFFFu, send, 8);
            h2[j] = (hi ? h1[j + 5] : h1[j]) + recv;
        }
    }
#pragma unroll
    for (int off = 4; off > 0; off >>= 1) {
#pragma unroll
        for (int j = 0; j < 5; j++)
            h2[j] += __shfl_xor_sync(0xFFFFFFFFu, h2[j], off);
    }

    // ---- Cross-warp reduction (4 warps) via sA ----
    __syncthreads();                    // all phase-2b shared reads done
    float* red    = (float*)sA;         // 4 warps * 20 scalars
    float* logits = (float*)sA + 4 * 20;
    const int wrp = q >> 5;
    if ((lane & 7) == 0) {
        int base = wrp * 20 + ((lane >> 3) & 3) * 5;
#pragma unroll
        for (int j = 0; j < 5; j++) red[base + j] = h2[j];
    }
    __syncthreads();

    if (q < NCLS) {
        float re = 0.f, im = 0.f;
#pragma unroll
        for (int wq2 = 0; wq2 < NT / 32; wq2++) {
            re += red[wq2 * 20 + 2 * q];
            im += red[wq2 * 20 + 2 * q + 1];
        }
        float r2v = re * re + im * im;
        // sin(atan2(im,re)) = im/|z|; dropped norms positive -> phases unchanged
        logits[q] = (r2v > 0.f) ? 5.0f * im * rsqrtf(r2v) : 0.0f;
    }
    __syncthreads();

    if (q < NCLS) {
        float m = -1e30f;
#pragma unroll
        for (int k = 0; k < NCLS; k++) m = fmaxf(m, logits[k]);
        float sum = 0.f;
#pragma unroll
        for (int k = 0; k < NCLS; k++) sum += __expf(logits[k] - m);
        out[(size_t)row * NCLS + q] = __expf(logits[q] - m) / sum;
    }
}

extern "C" void kernel_launch(void* const* d_in, const int* in_sizes, int n_in,
                              void* d_out, int out_size) {
    const float* x = (const float*)d_in[0];     // (8192, 2048) fp32
    const float* w = (const float*)d_in[1];     // (4096,) fp32
    float* out = (float*)d_out;                 // (8192, 10) fp32

    vpc_init<<<(N + 255) / 256, 256>>>(w);
    vpc_main<<<8192, NT>>>(x, w, out);
}